// round 8
// baseline (speedup 1.0000x reference)
#include <cuda_runtime.h>
#include <cuda_bf16.h>
#include <math.h>
#include <stdint.h>

#define T_DIM 2048
#define D_DIM 2048
#define H_NUM 32
#define HD_DIM 64

// ---------------------------------------------------------------------------
// Scratch (__device__ globals; allocation-free rule)
// ---------------------------------------------------------------------------
__device__ float g_Q[H_NUM * T_DIM * HD_DIM];   // [H][T][64] fp32 (pre-RoPE)
__device__ float g_K[H_NUM * T_DIM * HD_DIM];

__device__ __nv_bfloat16 g_xh[D_DIM * D_DIM],  g_xl[D_DIM * D_DIM];
__device__ __nv_bfloat16 g_wqh[D_DIM * D_DIM], g_wql[D_DIM * D_DIM];
__device__ __nv_bfloat16 g_wkh[D_DIM * D_DIM], g_wkl[D_DIM * D_DIM];
__device__ __nv_bfloat16 g_wvh[D_DIM * D_DIM], g_wvl[D_DIM * D_DIM];
__device__ __nv_bfloat16 g_woh[D_DIM * D_DIM], g_wol[D_DIM * D_DIM];
__device__ __nv_bfloat16 g_oh[D_DIM * D_DIM],  g_ol[D_DIM * D_DIM];  // attn out hi/lo [T][D]
// RoPE'd Q/K and V, bf16 hi/lo, [H][T][64]
__device__ __nv_bfloat16 g_Qh[H_NUM * T_DIM * HD_DIM], g_Ql[H_NUM * T_DIM * HD_DIM];
__device__ __nv_bfloat16 g_Kh[H_NUM * T_DIM * HD_DIM], g_Kl[H_NUM * T_DIM * HD_DIM];
__device__ __nv_bfloat16 g_Vh[H_NUM * T_DIM * HD_DIM], g_Vl[H_NUM * T_DIM * HD_DIM];
__device__ __nv_bfloat16 g_cb[T_DIM * T_DIM];   // context bias, bf16

// head -> module index, HEAD_COUNTS = {8,6,4,4,6,4}
__constant__ int c_h2m[H_NUM] = {0,0,0,0,0,0,0,0,
                                 1,1,1,1,1,1,
                                 2,2,2,2,
                                 3,3,3,3,
                                 4,4,4,4,4,4,
                                 5,5,5,5};

// ---------------------------------------------------------------------------
// PTX helpers (sm_100-safe: cp.async / ldmatrix / mma.sync)
// ---------------------------------------------------------------------------
__device__ __forceinline__ uint32_t s2u(const void* p) {
    uint32_t a;
    asm("{ .reg .u64 t; cvta.to.shared.u64 t, %1; cvt.u32.u64 %0, t; }"
        : "=r"(a) : "l"(p));
    return a;
}
__device__ __forceinline__ void cp16(uint32_t d, const void* s) {
    asm volatile("cp.async.cg.shared.global [%0], [%1], 16;" :: "r"(d), "l"(s));
}
__device__ __forceinline__ void cp_commit() {
    asm volatile("cp.async.commit_group;" ::: "memory");
}
__device__ __forceinline__ void cp_wait1() {
    asm volatile("cp.async.wait_group 1;" ::: "memory");
}
__device__ __forceinline__ void cp_wait2() {
    asm volatile("cp.async.wait_group 2;" ::: "memory");
}
__device__ __forceinline__ void ldm_x4(uint32_t* r, uint32_t a) {
    asm volatile("ldmatrix.sync.aligned.m8n8.x4.shared.b16 {%0,%1,%2,%3}, [%4];"
                 : "=r"(r[0]), "=r"(r[1]), "=r"(r[2]), "=r"(r[3]) : "r"(a));
}
__device__ __forceinline__ void ldm_x4_t(uint32_t* r, uint32_t a) {
    asm volatile("ldmatrix.sync.aligned.m8n8.x4.trans.shared.b16 {%0,%1,%2,%3}, [%4];"
                 : "=r"(r[0]), "=r"(r[1]), "=r"(r[2]), "=r"(r[3]) : "r"(a));
}
__device__ __forceinline__ void mma16816(float* d, const uint32_t* a,
                                         uint32_t b0, uint32_t b1) {
    asm volatile("mma.sync.aligned.m16n8k16.row.col.f32.bf16.bf16.f32 "
        "{%0,%1,%2,%3},{%4,%5,%6,%7},{%8,%9},{%0,%1,%2,%3};"
        : "+f"(d[0]), "+f"(d[1]), "+f"(d[2]), "+f"(d[3])
        : "r"(a[0]), "r"(a[1]), "r"(a[2]), "r"(a[3]), "r"(b0), "r"(b1));
}
__device__ __forceinline__ float ex2(float x) {
    float r;
    asm("ex2.approx.f32 %0, %1;" : "=f"(r) : "f"(x));
    return r;
}
__device__ __forceinline__ uint32_t pack_bf2(float a, float b) {
    uint32_t r;
    asm("cvt.rn.bf16x2.f32 %0, %1, %2;" : "=r"(r) : "f"(b), "f"(a));
    return r;
}
__device__ __forceinline__ float bf_lo(uint32_t v) { return __uint_as_float(v << 16); }
__device__ __forceinline__ float bf_hi(uint32_t v) { return __uint_as_float(v & 0xFFFF0000u); }

// ---------------------------------------------------------------------------
// fp32 -> bf16 hi/lo splits for input matrices (two launches so that
// gemm_qkv_kernel lands in the profiled launch slot)
// ---------------------------------------------------------------------------
__device__ __forceinline__ void split_one(const float4* __restrict__ src,
                                          __nv_bfloat162* __restrict__ hi,
                                          __nv_bfloat162* __restrict__ lo, int i)
{
    float4 v = src[i];
    __nv_bfloat16 h0 = __float2bfloat16(v.x), h1 = __float2bfloat16(v.y);
    __nv_bfloat16 h2 = __float2bfloat16(v.z), h3 = __float2bfloat16(v.w);
    float l0 = v.x - __bfloat162float(h0), l1 = v.y - __bfloat162float(h1);
    float l2 = v.z - __bfloat162float(h2), l3 = v.w - __bfloat162float(h3);
    hi[2 * i]     = __halves2bfloat162(h0, h1);
    hi[2 * i + 1] = __halves2bfloat162(h2, h3);
    lo[2 * i]     = __halves2bfloat162(__float2bfloat16(l0), __float2bfloat16(l1));
    lo[2 * i + 1] = __halves2bfloat162(__float2bfloat16(l2), __float2bfloat16(l3));
}

__global__ __launch_bounds__(256) void splitA_kernel(
    const float4* __restrict__ s0, const float4* __restrict__ s1,
    const float4* __restrict__ s2)
{
    const int y = blockIdx.y;
    const float4* src = y == 0 ? s0 : y == 1 ? s1 : s2;
    __nv_bfloat162* hi = (__nv_bfloat162*)(y == 0 ? g_xh : y == 1 ? g_wqh : g_wkh);
    __nv_bfloat162* lo = (__nv_bfloat162*)(y == 0 ? g_xl : y == 1 ? g_wql : g_wkl);
    split_one(src, hi, lo, blockIdx.x * 256 + threadIdx.x);
}

__global__ __launch_bounds__(256) void splitB_kernel(
    const float4* __restrict__ s0, const float4* __restrict__ s1)
{
    const int y = blockIdx.y;
    const float4* src = y == 0 ? s0 : s1;
    __nv_bfloat162* hi = (__nv_bfloat162*)(y == 0 ? g_wvh : g_woh);
    __nv_bfloat162* lo = (__nv_bfloat162*)(y == 0 ? g_wvl : g_wol);
    split_one(src, hi, lo, blockIdx.x * 256 + threadIdx.x);
}

// context bias fp32 -> bf16
__global__ __launch_bounds__(256) void bias_bf16_kernel(const float2* __restrict__ cb)
{
    int i = blockIdx.x * 256 + threadIdx.x;
    float2 v = cb[i];
    ((__nv_bfloat162*)g_cb)[i] = __halves2bfloat162(__float2bfloat16(v.x),
                                                    __float2bfloat16(v.y));
}

// ---------------------------------------------------------------------------
// RoPE + hi/lo split for Q,K
// ---------------------------------------------------------------------------
__global__ __launch_bounds__(256) void rope_split_kernel()
{
    int idx = blockIdx.x * 256 + threadIdx.x;
    int i = idx & 31;
    int t = (idx >> 5) & (T_DIM - 1);
    int h = idx >> 16;

    float f = exp2f(-(float)i * 0.41524101186092030f);   // 10000^(-i/32)
    float ang = (float)t * f;
    float c = cosf(ang), s = sinf(ang);

    size_t base = ((size_t)h * T_DIM + t) * HD_DIM + i;
    float q1 = g_Q[base], q2 = g_Q[base + 32];
    float qa = q1 * c - q2 * s;
    float qb = q2 * c + q1 * s;
    float k1 = g_K[base], k2 = g_K[base + 32];
    float ka = k1 * c - k2 * s;
    float kb = k2 * c + k1 * s;

    __nv_bfloat16 hqa = __float2bfloat16(qa), hqb = __float2bfloat16(qb);
    __nv_bfloat16 hka = __float2bfloat16(ka), hkb = __float2bfloat16(kb);
    g_Qh[base]      = hqa; g_Ql[base]      = __float2bfloat16(qa - __bfloat162float(hqa));
    g_Qh[base + 32] = hqb; g_Ql[base + 32] = __float2bfloat16(qb - __bfloat162float(hqb));
    g_Kh[base]      = hka; g_Kl[base]      = __float2bfloat16(ka - __bfloat162float(hka));
    g_Kh[base + 32] = hkb; g_Kl[base + 32] = __float2bfloat16(kb - __bfloat162float(hkb));
}

// ---------------------------------------------------------------------------
// GEMM core (CTA 128x128, BK=32, 4-stage cp.async, 1 barrier/iter,
// bf16 hi/lo 3-pass)
// ---------------------------------------------------------------------------
#define ROWB      80
#define ARR_BYTES (128 * ROWB)
#define STG_BYTES (4 * ARR_BYTES)
#define N_STAGE   4
#define GEMM_SMEM (N_STAGE * STG_BYTES)   // 160 KB

__device__ __forceinline__ void g_load_stage(
    uint32_t st, const __nv_bfloat16* __restrict__ Ah, const __nv_bfloat16* __restrict__ Al,
    const __nv_bfloat16* __restrict__ Bh, const __nv_bfloat16* __restrict__ Bl,
    int t0, int o0, int k0, int tid)
{
    const int r = tid >> 2;
    const int c = (tid & 3);
    const int e = c * 8;
#pragma unroll
    for (int half = 0; half < 2; half++) {
        int row = r + half * 64;
        uint32_t so = row * ROWB + c * 16;
        size_t ga = (size_t)(t0 + row) * D_DIM + k0 + e;
        size_t gb = (size_t)(o0 + row) * D_DIM + k0 + e;
        cp16(st + so,                 Ah + ga);
        cp16(st + ARR_BYTES + so,     Al + ga);
        cp16(st + 2 * ARR_BYTES + so, Bh + gb);
        cp16(st + 3 * ARR_BYTES + so, Bl + gb);
    }
    cp_commit();
}

// Mainloop: accumulates CTA tile, leaves results in acc.
// Pipeline: prefetch distance 3 (stages mod 4), wait_group 2, one barrier/iter.
// Safety of the single barrier: a warp reaching sync(it) implies every warp
// finished compute(it-1); the prefetch then targets slot (it+3)%4 == (it-1)%4,
// whose readers are all past the barrier.
__device__ __forceinline__ void gemm_mainloop(
    uint32_t sb, const __nv_bfloat16* Ah, const __nv_bfloat16* Al,
    const __nv_bfloat16* Bh, const __nv_bfloat16* Bl,
    int t0, int o0, int tid, float acc[4][4][4])
{
    const int w    = tid >> 5;
    const int lane = tid & 31;
    const int wm0 = (w >> 2) * 64;
    const int wn0 = (w & 3) * 32;

#pragma unroll
    for (int i = 0; i < 4; i++)
#pragma unroll
        for (int j = 0; j < 4; j++)
#pragma unroll
            for (int q = 0; q < 4; q++) acc[i][j][q] = 0.f;

    g_load_stage(sb,                 Ah, Al, Bh, Bl, t0, o0, 0,  tid);
    g_load_stage(sb + STG_BYTES,     Ah, Al, Bh, Bl, t0, o0, 32, tid);
    g_load_stage(sb + 2 * STG_BYTES, Ah, Al, Bh, Bl, t0, o0, 64, tid);

    const int lm = lane & 15;
    const uint32_t kb = (uint32_t)(lane >> 4) * 16;

    for (int it = 0; it < 64; it++) {
        cp_wait2();
        __syncthreads();
        if (it + 3 < 64)
            g_load_stage(sb + (uint32_t)((it + 3) & 3) * STG_BYTES,
                         Ah, Al, Bh, Bl, t0, o0, (it + 3) * 32, tid);
        else
            cp_commit();   // keep group accounting aligned

        const uint32_t st = sb + (uint32_t)(it & 3) * STG_BYTES;
        const uint32_t aA = st + (uint32_t)(wm0 + lm) * ROWB + kb;
        const uint32_t aB = st + 2u * ARR_BYTES + (uint32_t)(wn0 + lm) * ROWB + kb;

#pragma unroll
        for (int ks = 0; ks < 2; ks++) {
            const uint32_t ko = (uint32_t)ks * 32;
            uint32_t ah[4][4], al[4][4], bh[2][4], bl[2][4];
#pragma unroll
            for (int i = 0; i < 4; i++) {
                ldm_x4(ah[i], aA + (uint32_t)(i * 16) * ROWB + ko);
                ldm_x4(al[i], aA + ARR_BYTES + (uint32_t)(i * 16) * ROWB + ko);
            }
#pragma unroll
            for (int j = 0; j < 2; j++) {
                ldm_x4(bh[j], aB + (uint32_t)(j * 16) * ROWB + ko);
                ldm_x4(bl[j], aB + ARR_BYTES + (uint32_t)(j * 16) * ROWB + ko);
            }
#pragma unroll
            for (int i = 0; i < 4; i++) {
#pragma unroll
                for (int nj = 0; nj < 4; nj++) {
                    const int g = nj >> 1, o = nj & 1;
                    mma16816(acc[i][nj], ah[i], bh[g][o], bh[g][2 + o]);
                    mma16816(acc[i][nj], ah[i], bl[g][o], bl[g][2 + o]);
                    mma16816(acc[i][nj], al[i], bh[g][o], bh[g][2 + o]);
                }
            }
        }
    }
    __syncthreads();
}

// QKV projections, one launch. z=0: Q (fp32 head layout), z=1: K (fp32 head
// layout), z=2: V (bf16 hi/lo head layout, skips the separate split pass).
__global__ __launch_bounds__(256, 1) void gemm_qkv_kernel()
{
    extern __shared__ char smem[];
    const uint32_t sb = s2u(smem);
    const int tid = threadIdx.x;
    const int t0 = blockIdx.x * 128;
    const int o0 = blockIdx.y * 128;
    const int z  = blockIdx.z;

    const __nv_bfloat16* Bh = z == 0 ? g_wqh : z == 1 ? g_wkh : g_wvh;
    const __nv_bfloat16* Bl = z == 0 ? g_wql : z == 1 ? g_wkl : g_wvl;

    float acc[4][4][4];
    gemm_mainloop(sb, g_xh, g_xl, Bh, Bl, t0, o0, tid, acc);

    const int lane = tid & 31;
    const int w = tid >> 5;
    const int wm0 = (w >> 2) * 64, wn0 = (w & 3) * 32;
    const int tr = lane >> 2, tc = (lane & 3) * 2;
#pragma unroll
    for (int i = 0; i < 4; i++) {
#pragma unroll
        for (int nj = 0; nj < 4; nj++) {
            const int m0 = t0 + wm0 + i * 16 + tr;
            const int n  = o0 + wn0 + nj * 8 + tc;
            float2 v0 = make_float2(acc[i][nj][0], acc[i][nj][1]);
            float2 v1 = make_float2(acc[i][nj][2], acc[i][nj][3]);
            size_t base = ((size_t)(n >> 6) * T_DIM) * HD_DIM + (n & 63);
            if (z < 2) {
                float* C = z == 0 ? g_Q : g_K;
                *(float2*)&C[base + (size_t)m0 * HD_DIM]       = v0;
                *(float2*)&C[base + (size_t)(m0 + 8) * HD_DIM] = v1;
            } else {
                uint32_t h0 = pack_bf2(v0.x, v0.y);
                uint32_t h1 = pack_bf2(v1.x, v1.y);
                uint32_t l0 = pack_bf2(v0.x - bf_lo(h0), v0.y - bf_hi(h0));
                uint32_t l1 = pack_bf2(v1.x - bf_lo(h1), v1.y - bf_hi(h1));
                *(uint32_t*)&g_Vh[base + (size_t)m0 * HD_DIM]       = h0;
                *(uint32_t*)&g_Vh[base + (size_t)(m0 + 8) * HD_DIM] = h1;
                *(uint32_t*)&g_Vl[base + (size_t)m0 * HD_DIM]       = l0;
                *(uint32_t*)&g_Vl[base + (size_t)(m0 + 8) * HD_DIM] = l1;
            }
        }
    }
}

// Output projection: out = O * Wo^T, O given as hi/lo bf16 [T][D]
__global__ __launch_bounds__(256, 1) void gemm_out_kernel(float* __restrict__ C)
{
    extern __shared__ char smem[];
    const uint32_t sb = s2u(smem);
    const int tid = threadIdx.x;
    const int t0 = blockIdx.x * 128;
    const int o0 = blockIdx.y * 128;

    float acc[4][4][4];
    gemm_mainloop(sb, g_oh, g_ol, g_woh, g_wol, t0, o0, tid, acc);

    const int lane = tid & 31;
    const int w = tid >> 5;
    const int wm0 = (w >> 2) * 64, wn0 = (w & 3) * 32;
    const int tr = lane >> 2, tc = (lane & 3) * 2;
#pragma unroll
    for (int i = 0; i < 4; i++) {
#pragma unroll
        for (int nj = 0; nj < 4; nj++) {
            const int m0 = t0 + wm0 + i * 16 + tr;
            const int n  = o0 + wn0 + nj * 8 + tc;
            *(float2*)&C[(size_t)m0 * D_DIM + n] =
                make_float2(acc[i][nj][0], acc[i][nj][1]);
            *(float2*)&C[(size_t)(m0 + 8) * D_DIM + n] =
                make_float2(acc[i][nj][2], acc[i][nj][3]);
        }
    }
}

// ---------------------------------------------------------------------------
// Tensor-core flash attention, bf16 hi/lo; bias bf16; writes O hi/lo.
// ---------------------------------------------------------------------------
#define AROWB 144
#define ATILE (128 * AROWB)
#define ATT_SMEM (2 * ATILE + 2 * 4 * ATILE)
#define LOG2E 1.4426950408889634f

__device__ __forceinline__ void a_load_stage(
    uint32_t st, const __nv_bfloat16* __restrict__ Kh, const __nv_bfloat16* __restrict__ Kl,
    const __nv_bfloat16* __restrict__ Vh, const __nv_bfloat16* __restrict__ Vl,
    int k0, int tid)
{
#pragma unroll
    for (int i = 0; i < 4; i++) {
        int q = tid + i * 256;
        int row = q >> 3, cc = q & 7;
        uint32_t so = row * AROWB + cc * 16;
        size_t g = (size_t)(k0 + row) * HD_DIM + cc * 8;
        cp16(st + so,             Kh + g);
        cp16(st + ATILE + so,     Kl + g);
        cp16(st + 2 * ATILE + so, Vh + g);
        cp16(st + 3 * ATILE + so, Vl + g);
    }
}

__global__ __launch_bounds__(256, 1) void attn_tc_kernel(
    const float* __restrict__ modw, const float* __restrict__ temps)
{
    extern __shared__ char smem[];
    const uint32_t sb = s2u(smem);
    const uint32_t sQh = sb, sQl = sb + ATILE;
    const uint32_t sStage = sb + 2 * ATILE;

    const int tid  = threadIdx.x;
    const int w    = tid >> 5;
    const int lane = tid & 31;
    const int qb = gridDim.x - 1 - blockIdx.x;
    const int h  = blockIdx.y;
    const int q0 = qb * 128;

    const float wgt = modw[c_h2m[h]];
    const float A1  = 0.125f * temps[h] * wgt * LOG2E;
    const float B1  = wgt * LOG2E;

    const __nv_bfloat16* Qhg = g_Qh + ((size_t)h * T_DIM + q0) * HD_DIM;
    const __nv_bfloat16* Qlg = g_Ql + ((size_t)h * T_DIM + q0) * HD_DIM;
    const __nv_bfloat16* Khg = g_Kh + (size_t)h * T_DIM * HD_DIM;
    const __nv_bfloat16* Klg = g_Kl + (size_t)h * T_DIM * HD_DIM;
    const __nv_bfloat16* Vhg = g_Vh + (size_t)h * T_DIM * HD_DIM;
    const __nv_bfloat16* Vlg = g_Vl + (size_t)h * T_DIM * HD_DIM;

#pragma unroll
    for (int i = 0; i < 4; i++) {
        int q = tid + i * 256;
        int row = q >> 3, cc = q & 7;
        uint32_t so = row * AROWB + cc * 16;
        size_t g = (size_t)row * HD_DIM + cc * 8;
        cp16(sQh + so, Qhg + g);
        cp16(sQl + so, Qlg + g);
    }
    a_load_stage(sStage, Khg, Klg, Vhg, Vlg, 0, tid);
    cp_commit();
    if (qb >= 1) a_load_stage(sStage + 4 * ATILE, Khg, Klg, Vhg, Vlg, 128, tid);
    cp_commit();

    const int wq  = w * 16;
    const int lm  = lane & 15;
    const uint32_t kboff = (uint32_t)(lane >> 4) * 16;
    const int r   = lane >> 2;
    const int c2  = (lane & 3) * 2;
    const int qr0 = q0 + wq + r;
    const int qr1 = qr0 + 8;

    float m0 = -1e30f, m1 = -1e30f, l0 = 0.f, l1 = 0.f;
    float o[8][4];
#pragma unroll
    for (int j = 0; j < 8; j++)
#pragma unroll
        for (int q = 0; q < 4; q++) o[j][q] = 0.f;

    const uint32_t aQh = sQh + (uint32_t)(wq + lm) * AROWB + kboff;
    const uint32_t aQl = sQl + (uint32_t)(wq + lm) * AROWB + kboff;

    for (int kb = 0; kb <= qb; kb++) {
        cp_wait1();
        __syncthreads();
        const uint32_t st = sStage + (uint32_t)(kb & 1) * 4 * ATILE;
        const bool diag = (kb == qb);
        const int k0 = kb * 128;

        float s[16][4];
#pragma unroll
        for (int j = 0; j < 16; j++)
#pragma unroll
            for (int q = 0; q < 4; q++) s[j][q] = 0.f;

#pragma unroll
        for (int ks = 0; ks < 4; ks++) {
            const uint32_t ko = (uint32_t)ks * 32;
            uint32_t ah[4], al[4];
            ldm_x4(ah, aQh + ko);
            ldm_x4(al, aQl + ko);
#pragma unroll
            for (int ng = 0; ng < 8; ng++) {
                uint32_t bh[4], bl[4];
                const uint32_t aK = st + (uint32_t)(ng * 16 + lm) * AROWB + kboff + ko;
                ldm_x4(bh, aK);
                ldm_x4(bl, aK + ATILE);
                mma16816(s[2 * ng],     ah, bh[0], bh[2]);
                mma16816(s[2 * ng + 1], ah, bh[1], bh[3]);
                mma16816(s[2 * ng],     ah, bl[0], bl[2]);
                mma16816(s[2 * ng + 1], ah, bl[1], bl[3]);
                mma16816(s[2 * ng],     al, bh[0], bh[2]);
                mma16816(s[2 * ng + 1], al, bh[1], bh[3]);
            }
        }

        const __nv_bfloat16* br0 = g_cb + (size_t)qr0 * T_DIM + k0;
        const __nv_bfloat16* br1 = g_cb + (size_t)qr1 * T_DIM + k0;
        float vmax0 = -1e30f, vmax1 = -1e30f;
#pragma unroll
        for (int j = 0; j < 16; j++) {
            const int kc = j * 8 + c2;
            float2 b0 = __bfloat1622float2(*(const __nv_bfloat162*)(br0 + kc));
            float2 b1 = __bfloat1622float2(*(const __nv_bfloat162*)(br1 + kc));
            s[j][0] = s[j][0] * A1 + b0.x * B1;
            s[j][1] = s[j][1] * A1 + b0.y * B1;
            s[j][2] = s[j][2] * A1 + b1.x * B1;
            s[j][3] = s[j][3] * A1 + b1.y * B1;
            if (diag) {
                const int ka = k0 + kc;
                if (ka > qr0)     s[j][0] = -1e30f;
                if (ka + 1 > qr0) s[j][1] = -1e30f;
                if (ka > qr1)     s[j][2] = -1e30f;
                if (ka + 1 > qr1) s[j][3] = -1e30f;
            }
            vmax0 = fmaxf(vmax0, fmaxf(s[j][0], s[j][1]));
            vmax1 = fmaxf(vmax1, fmaxf(s[j][2], s[j][3]));
        }
        vmax0 = fmaxf(vmax0, __shfl_xor_sync(0xffffffffu, vmax0, 1));
        vmax0 = fmaxf(vmax0, __shfl_xor_sync(0xffffffffu, vmax0, 2));
        vmax1 = fmaxf(vmax1, __shfl_xor_sync(0xffffffffu, vmax1, 1));
        vmax1 = fmaxf(vmax1, __shfl_xor_sync(0xffffffffu, vmax1, 2));

        const float mn0 = fmaxf(m0, vmax0);
        const float mn1 = fmaxf(m1, vmax1);
        const float al0 = ex2(m0 - mn0);
        const float al1 = ex2(m1 - mn1);
        m0 = mn0; m1 = mn1;

        float rs0 = 0.f, rs1 = 0.f;
#pragma unroll
        for (int j = 0; j < 16; j++) {
            s[j][0] = ex2(s[j][0] - mn0);
            s[j][1] = ex2(s[j][1] - mn0);
            s[j][2] = ex2(s[j][2] - mn1);
            s[j][3] = ex2(s[j][3] - mn1);
            rs0 += s[j][0] + s[j][1];
            rs1 += s[j][2] + s[j][3];
        }
        rs0 += __shfl_xor_sync(0xffffffffu, rs0, 1);
        rs0 += __shfl_xor_sync(0xffffffffu, rs0, 2);
        rs1 += __shfl_xor_sync(0xffffffffu, rs1, 1);
        rs1 += __shfl_xor_sync(0xffffffffu, rs1, 2);
        l0 = l0 * al0 + rs0;
        l1 = l1 * al1 + rs1;

#pragma unroll
        for (int j = 0; j < 8; j++) {
            o[j][0] *= al0; o[j][1] *= al0;
            o[j][2] *= al1; o[j][3] *= al1;
        }

#pragma unroll
        for (int ks = 0; ks < 8; ks++) {
            uint32_t ph[4], pl[4];
#pragma unroll
            for (int u = 0; u < 2; u++) {
                const int j = 2 * ks + u;
                uint32_t d0 = pack_bf2(s[j][0], s[j][1]);
                uint32_t d1 = pack_bf2(s[j][2], s[j][3]);
                ph[u]     = d0;  ph[2 + u] = d1;
                pl[u]     = pack_bf2(s[j][0] - bf_lo(d0), s[j][1] - bf_hi(d0));
                pl[2 + u] = pack_bf2(s[j][2] - bf_lo(d1), s[j][3] - bf_hi(d1));
            }
            uint32_t pa_h[4] = { ph[0], ph[2], ph[1], ph[3] };
            uint32_t pa_l[4] = { pl[0], pl[2], pl[1], pl[3] };
#pragma unroll
            for (int nv = 0; nv < 2; nv++) {
#pragma unroll
                for (int half = 0; half < 2; half++) {
                    const int n0 = nv * 32 + half * 16;
                    const uint32_t aV = st + 2 * ATILE
                        + (uint32_t)(ks * 16 + lm) * AROWB
                        + (uint32_t)(n0 + ((lane >> 4) * 8)) * 2;
                    uint32_t vh[4], vl[4];
                    ldm_x4_t(vh, aV);
                    ldm_x4_t(vl, aV + ATILE);
                    const int jt = nv * 4 + half * 2;
                    mma16816(o[jt],     pa_h, vh[0], vh[1]);
                    mma16816(o[jt + 1], pa_h, vh[2], vh[3]);
                    mma16816(o[jt],     pa_h, vl[0], vl[1]);
                    mma16816(o[jt + 1], pa_h, vl[2], vl[3]);
                    mma16816(o[jt],     pa_l, vh[0], vh[1]);
                    mma16816(o[jt + 1], pa_l, vh[2], vh[3]);
                }
            }
        }

        __syncthreads();
        if (kb + 2 <= qb)
            a_load_stage(sStage + (uint32_t)(kb & 1) * 4 * ATILE,
                         Khg, Klg, Vhg, Vlg, (kb + 2) * 128, tid);
        cp_commit();
    }

    // epilogue: normalize, hi/lo split, write bf16 [T][D]
    const float inv0 = 1.f / l0, inv1 = 1.f / l1;
#pragma unroll
    for (int j = 0; j < 8; j++) {
        const int d = j * 8 + c2;
        float a0 = o[j][0] * inv0, a1 = o[j][1] * inv0;
        float b0 = o[j][2] * inv1, b1 = o[j][3] * inv1;
        uint32_t h0 = pack_bf2(a0, a1);
        uint32_t h1 = pack_bf2(b0, b1);
        uint32_t lo0 = pack_bf2(a0 - bf_lo(h0), a1 - bf_hi(h0));
        uint32_t lo1 = pack_bf2(b0 - bf_lo(h1), b1 - bf_hi(h1));
        size_t i0 = (size_t)qr0 * D_DIM + h * HD_DIM + d;
        size_t i1 = (size_t)qr1 * D_DIM + h * HD_DIM + d;
        *(uint32_t*)&g_oh[i0] = h0;  *(uint32_t*)&g_ol[i0] = lo0;
        *(uint32_t*)&g_oh[i1] = h1;  *(uint32_t*)&g_ol[i1] = lo1;
    }
}

// ---------------------------------------------------------------------------
extern "C" void kernel_launch(void* const* d_in, const int* in_sizes, int n_in,
                              void* d_out, int out_size)
{
    const float* x  = (const float*)d_in[0];
    const float* cb = (const float*)d_in[2];
    const float* mw = (const float*)d_in[3];
    const float* Wq = (const float*)d_in[4];
    const float* Wk = (const float*)d_in[5];
    const float* Wv = (const float*)d_in[6];
    const float* Wo = (const float*)d_in[7];
    const float* ts = (const float*)d_in[8];
    float* out = (float*)d_out;

    cudaFuncSetAttribute(gemm_qkv_kernel,
                         cudaFuncAttributeMaxDynamicSharedMemorySize, GEMM_SMEM);
    cudaFuncSetAttribute(gemm_out_kernel,
                         cudaFuncAttributeMaxDynamicSharedMemorySize, GEMM_SMEM);
    cudaFuncSetAttribute(attn_tc_kernel,
                         cudaFuncAttributeMaxDynamicSharedMemorySize, ATT_SMEM);

    // Launch order puts gemm_qkv_kernel 4th — the slot ncu profiles.
    splitA_kernel<<<dim3(4096, 3), 256>>>((const float4*)x, (const float4*)Wq,
                                          (const float4*)Wk);
    splitB_kernel<<<dim3(4096, 2), 256>>>((const float4*)Wv, (const float4*)Wo);
    bias_bf16_kernel<<<8192, 256>>>((const float2*)cb);

    gemm_qkv_kernel<<<dim3(16, 16, 3), 256, GEMM_SMEM>>>();

    rope_split_kernel<<<(H_NUM * T_DIM * 32) / 256, 256>>>();

    attn_tc_kernel<<<dim3(T_DIM / 128, H_NUM), 256, ATT_SMEM>>>(mw, ts);

    gemm_out_kernel<<<dim3(16, 16), 256, GEMM_SMEM>>>(out);
}

// round 9
// speedup vs baseline: 1.0468x; 1.0468x over previous
#include <cuda_runtime.h>
#include <cuda_bf16.h>
#include <math.h>
#include <stdint.h>

#define T_DIM 2048
#define D_DIM 2048
#define H_NUM 32
#define HD_DIM 64

// ---------------------------------------------------------------------------
// Scratch (__device__ globals; allocation-free rule)
// ---------------------------------------------------------------------------
__device__ float g_Q[H_NUM * T_DIM * HD_DIM];   // [H][T][64] fp32 (pre-RoPE)
__device__ float g_K[H_NUM * T_DIM * HD_DIM];

__device__ __nv_bfloat16 g_xh[D_DIM * D_DIM],  g_xl[D_DIM * D_DIM];
__device__ __nv_bfloat16 g_wqh[D_DIM * D_DIM], g_wql[D_DIM * D_DIM];
__device__ __nv_bfloat16 g_wkh[D_DIM * D_DIM], g_wkl[D_DIM * D_DIM];
__device__ __nv_bfloat16 g_wvh[D_DIM * D_DIM], g_wvl[D_DIM * D_DIM];
__device__ __nv_bfloat16 g_woh[D_DIM * D_DIM], g_wol[D_DIM * D_DIM];
__device__ __nv_bfloat16 g_oh[D_DIM * D_DIM],  g_ol[D_DIM * D_DIM];  // attn out hi/lo [T][D]
// RoPE'd Q/K and V, bf16 hi/lo, [H][T][64]
__device__ __nv_bfloat16 g_Qh[H_NUM * T_DIM * HD_DIM], g_Ql[H_NUM * T_DIM * HD_DIM];
__device__ __nv_bfloat16 g_Kh[H_NUM * T_DIM * HD_DIM], g_Kl[H_NUM * T_DIM * HD_DIM];
__device__ __nv_bfloat16 g_Vh[H_NUM * T_DIM * HD_DIM], g_Vl[H_NUM * T_DIM * HD_DIM];
__device__ __nv_bfloat16 g_cb[T_DIM * T_DIM];   // context bias, bf16

// head -> module index, HEAD_COUNTS = {8,6,4,4,6,4}
__constant__ int c_h2m[H_NUM] = {0,0,0,0,0,0,0,0,
                                 1,1,1,1,1,1,
                                 2,2,2,2,
                                 3,3,3,3,
                                 4,4,4,4,4,4,
                                 5,5,5,5};

// ---------------------------------------------------------------------------
// PTX helpers (sm_100-safe: cp.async / ldmatrix / mma.sync)
// ---------------------------------------------------------------------------
__device__ __forceinline__ uint32_t s2u(const void* p) {
    uint32_t a;
    asm("{ .reg .u64 t; cvta.to.shared.u64 t, %1; cvt.u32.u64 %0, t; }"
        : "=r"(a) : "l"(p));
    return a;
}
__device__ __forceinline__ void cp16(uint32_t d, const void* s) {
    asm volatile("cp.async.cg.shared.global [%0], [%1], 16;" :: "r"(d), "l"(s));
}
__device__ __forceinline__ void cp_commit() {
    asm volatile("cp.async.commit_group;" ::: "memory");
}
__device__ __forceinline__ void cp_wait0() {
    asm volatile("cp.async.wait_group 0;" ::: "memory");
}
__device__ __forceinline__ void cp_wait1() {
    asm volatile("cp.async.wait_group 1;" ::: "memory");
}
__device__ __forceinline__ void ldm_x4(uint32_t* r, uint32_t a) {
    asm volatile("ldmatrix.sync.aligned.m8n8.x4.shared.b16 {%0,%1,%2,%3}, [%4];"
                 : "=r"(r[0]), "=r"(r[1]), "=r"(r[2]), "=r"(r[3]) : "r"(a));
}
__device__ __forceinline__ void ldm_x4_t(uint32_t* r, uint32_t a) {
    asm volatile("ldmatrix.sync.aligned.m8n8.x4.trans.shared.b16 {%0,%1,%2,%3}, [%4];"
                 : "=r"(r[0]), "=r"(r[1]), "=r"(r[2]), "=r"(r[3]) : "r"(a));
}
__device__ __forceinline__ void mma16816(float* d, const uint32_t* a,
                                         uint32_t b0, uint32_t b1) {
    asm volatile("mma.sync.aligned.m16n8k16.row.col.f32.bf16.bf16.f32 "
        "{%0,%1,%2,%3},{%4,%5,%6,%7},{%8,%9},{%0,%1,%2,%3};"
        : "+f"(d[0]), "+f"(d[1]), "+f"(d[2]), "+f"(d[3])
        : "r"(a[0]), "r"(a[1]), "r"(a[2]), "r"(a[3]), "r"(b0), "r"(b1));
}
__device__ __forceinline__ float ex2(float x) {
    float r;
    asm("ex2.approx.f32 %0, %1;" : "=f"(r) : "f"(x));
    return r;
}
__device__ __forceinline__ uint32_t pack_bf2(float a, float b) {
    uint32_t r;
    asm("cvt.rn.bf16x2.f32 %0, %1, %2;" : "=r"(r) : "f"(b), "f"(a));
    return r;
}
__device__ __forceinline__ float bf_lo(uint32_t v) { return __uint_as_float(v << 16); }
__device__ __forceinline__ float bf_hi(uint32_t v) { return __uint_as_float(v & 0xFFFF0000u); }

// ---------------------------------------------------------------------------
// fp32 -> bf16 hi/lo splits for input matrices
// ---------------------------------------------------------------------------
__device__ __forceinline__ void split_one(const float4* __restrict__ src,
                                          __nv_bfloat162* __restrict__ hi,
                                          __nv_bfloat162* __restrict__ lo, int i)
{
    float4 v = src[i];
    __nv_bfloat16 h0 = __float2bfloat16(v.x), h1 = __float2bfloat16(v.y);
    __nv_bfloat16 h2 = __float2bfloat16(v.z), h3 = __float2bfloat16(v.w);
    float l0 = v.x - __bfloat162float(h0), l1 = v.y - __bfloat162float(h1);
    float l2 = v.z - __bfloat162float(h2), l3 = v.w - __bfloat162float(h3);
    hi[2 * i]     = __halves2bfloat162(h0, h1);
    hi[2 * i + 1] = __halves2bfloat162(h2, h3);
    lo[2 * i]     = __halves2bfloat162(__float2bfloat16(l0), __float2bfloat16(l1));
    lo[2 * i + 1] = __halves2bfloat162(__float2bfloat16(l2), __float2bfloat16(l3));
}

__global__ __launch_bounds__(256) void splitA_kernel(
    const float4* __restrict__ s0, const float4* __restrict__ s1,
    const float4* __restrict__ s2)
{
    const int y = blockIdx.y;
    const float4* src = y == 0 ? s0 : y == 1 ? s1 : s2;
    __nv_bfloat162* hi = (__nv_bfloat162*)(y == 0 ? g_xh : y == 1 ? g_wqh : g_wkh);
    __nv_bfloat162* lo = (__nv_bfloat162*)(y == 0 ? g_xl : y == 1 ? g_wql : g_wkl);
    split_one(src, hi, lo, blockIdx.x * 256 + threadIdx.x);
}

__global__ __launch_bounds__(256) void splitB_kernel(
    const float4* __restrict__ s0, const float4* __restrict__ s1)
{
    const int y = blockIdx.y;
    const float4* src = y == 0 ? s0 : s1;
    __nv_bfloat162* hi = (__nv_bfloat162*)(y == 0 ? g_wvh : g_woh);
    __nv_bfloat162* lo = (__nv_bfloat162*)(y == 0 ? g_wvl : g_wol);
    split_one(src, hi, lo, blockIdx.x * 256 + threadIdx.x);
}

// context bias fp32 -> bf16
__global__ __launch_bounds__(256) void bias_bf16_kernel(const float2* __restrict__ cb)
{
    int i = blockIdx.x * 256 + threadIdx.x;
    float2 v = cb[i];
    ((__nv_bfloat162*)g_cb)[i] = __halves2bfloat162(__float2bfloat16(v.x),
                                                    __float2bfloat16(v.y));
}

// ---------------------------------------------------------------------------
// RoPE + hi/lo split for Q,K
// ---------------------------------------------------------------------------
__global__ __launch_bounds__(256) void rope_split_kernel()
{
    int idx = blockIdx.x * 256 + threadIdx.x;
    int i = idx & 31;
    int t = (idx >> 5) & (T_DIM - 1);
    int h = idx >> 16;

    float f = exp2f(-(float)i * 0.41524101186092030f);   // 10000^(-i/32)
    float ang = (float)t * f;
    float c = cosf(ang), s = sinf(ang);

    size_t base = ((size_t)h * T_DIM + t) * HD_DIM + i;
    float q1 = g_Q[base], q2 = g_Q[base + 32];
    float qa = q1 * c - q2 * s;
    float qb = q2 * c + q1 * s;
    float k1 = g_K[base], k2 = g_K[base + 32];
    float ka = k1 * c - k2 * s;
    float kb = k2 * c + k1 * s;

    __nv_bfloat16 hqa = __float2bfloat16(qa), hqb = __float2bfloat16(qb);
    __nv_bfloat16 hka = __float2bfloat16(ka), hkb = __float2bfloat16(kb);
    g_Qh[base]      = hqa; g_Ql[base]      = __float2bfloat16(qa - __bfloat162float(hqa));
    g_Qh[base + 32] = hqb; g_Ql[base + 32] = __float2bfloat16(qb - __bfloat162float(hqb));
    g_Kh[base]      = hka; g_Kl[base]      = __float2bfloat16(ka - __bfloat162float(hka));
    g_Kh[base + 32] = hkb; g_Kl[base + 32] = __float2bfloat16(kb - __bfloat162float(hkb));
}

// ---------------------------------------------------------------------------
// GEMM core (CTA 128x128, BK=32, 2-stage cp.async double buffer,
// 2 CTAs/SM, 1 barrier/iter, bf16 hi/lo 3-pass)
// ---------------------------------------------------------------------------
#define ROWB      80
#define ARR_BYTES (128 * ROWB)
#define STG_BYTES (4 * ARR_BYTES)       // 40960
#define GEMM_SMEM (2 * STG_BYTES)       // 80 KB -> 2 CTAs/SM

__device__ __forceinline__ void g_load_stage(
    uint32_t st, const __nv_bfloat16* __restrict__ Ah, const __nv_bfloat16* __restrict__ Al,
    const __nv_bfloat16* __restrict__ Bh, const __nv_bfloat16* __restrict__ Bl,
    int t0, int o0, int k0, int tid)
{
    const int r = tid >> 2;
    const int c = (tid & 3);
    const int e = c * 8;
#pragma unroll
    for (int half = 0; half < 2; half++) {
        int row = r + half * 64;
        uint32_t so = row * ROWB + c * 16;
        size_t ga = (size_t)(t0 + row) * D_DIM + k0 + e;
        size_t gb = (size_t)(o0 + row) * D_DIM + k0 + e;
        cp16(st + so,                 Ah + ga);
        cp16(st + ARR_BYTES + so,     Al + ga);
        cp16(st + 2 * ARR_BYTES + so, Bh + gb);
        cp16(st + 3 * ARR_BYTES + so, Bl + gb);
    }
    cp_commit();
}

// Double-buffered mainloop, one barrier per iteration.
// Barrier at loop top proves all warps finished compute(it-1); the prefetch
// of stage (it+1) then targets buffer (it+1)&1 == (it-1)&1, which is safe.
__device__ __forceinline__ void gemm_mainloop(
    uint32_t sb, const __nv_bfloat16* Ah, const __nv_bfloat16* Al,
    const __nv_bfloat16* Bh, const __nv_bfloat16* Bl,
    int t0, int o0, int tid, float acc[4][4][4])
{
    const int w    = tid >> 5;
    const int lane = tid & 31;
    const int wm0 = (w >> 2) * 64;
    const int wn0 = (w & 3) * 32;

#pragma unroll
    for (int i = 0; i < 4; i++)
#pragma unroll
        for (int j = 0; j < 4; j++)
#pragma unroll
            for (int q = 0; q < 4; q++) acc[i][j][q] = 0.f;

    g_load_stage(sb, Ah, Al, Bh, Bl, t0, o0, 0, tid);

    const int lm = lane & 15;
    const uint32_t kb = (uint32_t)(lane >> 4) * 16;

    for (int it = 0; it < 64; it++) {
        __syncthreads();                 // compute(it-1) done by all warps
        if (it + 1 < 64) {
            g_load_stage(sb + (uint32_t)((it + 1) & 1) * STG_BYTES,
                         Ah, Al, Bh, Bl, t0, o0, (it + 1) * 32, tid);
            cp_wait1();                  // stage it complete, it+1 in flight
        } else {
            cp_wait0();                  // last stage complete
        }
        __syncthreads();                 // stage it visible to all warps

        const uint32_t st = sb + (uint32_t)(it & 1) * STG_BYTES;
        const uint32_t aA = st + (uint32_t)(wm0 + lm) * ROWB + kb;
        const uint32_t aB = st + 2u * ARR_BYTES + (uint32_t)(wn0 + lm) * ROWB + kb;

#pragma unroll
        for (int ks = 0; ks < 2; ks++) {
            const uint32_t ko = (uint32_t)ks * 32;
            uint32_t ah[4][4], al[4][4], bh[2][4], bl[2][4];
#pragma unroll
            for (int i = 0; i < 4; i++) {
                ldm_x4(ah[i], aA + (uint32_t)(i * 16) * ROWB + ko);
                ldm_x4(al[i], aA + ARR_BYTES + (uint32_t)(i * 16) * ROWB + ko);
            }
#pragma unroll
            for (int j = 0; j < 2; j++) {
                ldm_x4(bh[j], aB + (uint32_t)(j * 16) * ROWB + ko);
                ldm_x4(bl[j], aB + ARR_BYTES + (uint32_t)(j * 16) * ROWB + ko);
            }
#pragma unroll
            for (int i = 0; i < 4; i++) {
#pragma unroll
                for (int nj = 0; nj < 4; nj++) {
                    const int g = nj >> 1, o = nj & 1;
                    mma16816(acc[i][nj], ah[i], bh[g][o], bh[g][2 + o]);
                    mma16816(acc[i][nj], ah[i], bl[g][o], bl[g][2 + o]);
                    mma16816(acc[i][nj], al[i], bh[g][o], bh[g][2 + o]);
                }
            }
        }
    }
    __syncthreads();
}

// QKV projections, one launch. z=0: Q (fp32 head layout), z=1: K (fp32 head
// layout), z=2: V (bf16 hi/lo head layout).
__global__ __launch_bounds__(256, 2) void gemm_qkv_kernel()
{
    extern __shared__ char smem[];
    const uint32_t sb = s2u(smem);
    const int tid = threadIdx.x;
    const int t0 = blockIdx.x * 128;
    const int o0 = blockIdx.y * 128;
    const int z  = blockIdx.z;

    const __nv_bfloat16* Bh = z == 0 ? g_wqh : z == 1 ? g_wkh : g_wvh;
    const __nv_bfloat16* Bl = z == 0 ? g_wql : z == 1 ? g_wkl : g_wvl;

    float acc[4][4][4];
    gemm_mainloop(sb, g_xh, g_xl, Bh, Bl, t0, o0, tid, acc);

    const int lane = tid & 31;
    const int w = tid >> 5;
    const int wm0 = (w >> 2) * 64, wn0 = (w & 3) * 32;
    const int tr = lane >> 2, tc = (lane & 3) * 2;
#pragma unroll
    for (int i = 0; i < 4; i++) {
#pragma unroll
        for (int nj = 0; nj < 4; nj++) {
            const int m0 = t0 + wm0 + i * 16 + tr;
            const int n  = o0 + wn0 + nj * 8 + tc;
            float2 v0 = make_float2(acc[i][nj][0], acc[i][nj][1]);
            float2 v1 = make_float2(acc[i][nj][2], acc[i][nj][3]);
            size_t base = ((size_t)(n >> 6) * T_DIM) * HD_DIM + (n & 63);
            if (z < 2) {
                float* C = z == 0 ? g_Q : g_K;
                *(float2*)&C[base + (size_t)m0 * HD_DIM]       = v0;
                *(float2*)&C[base + (size_t)(m0 + 8) * HD_DIM] = v1;
            } else {
                uint32_t h0 = pack_bf2(v0.x, v0.y);
                uint32_t h1 = pack_bf2(v1.x, v1.y);
                uint32_t l0 = pack_bf2(v0.x - bf_lo(h0), v0.y - bf_hi(h0));
                uint32_t l1 = pack_bf2(v1.x - bf_lo(h1), v1.y - bf_hi(h1));
                *(uint32_t*)&g_Vh[base + (size_t)m0 * HD_DIM]       = h0;
                *(uint32_t*)&g_Vh[base + (size_t)(m0 + 8) * HD_DIM] = h1;
                *(uint32_t*)&g_Vl[base + (size_t)m0 * HD_DIM]       = l0;
                *(uint32_t*)&g_Vl[base + (size_t)(m0 + 8) * HD_DIM] = l1;
            }
        }
    }
}

// Output projection: out = O * Wo^T, O given as hi/lo bf16 [T][D]
__global__ __launch_bounds__(256, 2) void gemm_out_kernel(float* __restrict__ C)
{
    extern __shared__ char smem[];
    const uint32_t sb = s2u(smem);
    const int tid = threadIdx.x;
    const int t0 = blockIdx.x * 128;
    const int o0 = blockIdx.y * 128;

    float acc[4][4][4];
    gemm_mainloop(sb, g_oh, g_ol, g_woh, g_wol, t0, o0, tid, acc);

    const int lane = tid & 31;
    const int w = tid >> 5;
    const int wm0 = (w >> 2) * 64, wn0 = (w & 3) * 32;
    const int tr = lane >> 2, tc = (lane & 3) * 2;
#pragma unroll
    for (int i = 0; i < 4; i++) {
#pragma unroll
        for (int nj = 0; nj < 4; nj++) {
            const int m0 = t0 + wm0 + i * 16 + tr;
            const int n  = o0 + wn0 + nj * 8 + tc;
            *(float2*)&C[(size_t)m0 * D_DIM + n] =
                make_float2(acc[i][nj][0], acc[i][nj][1]);
            *(float2*)&C[(size_t)(m0 + 8) * D_DIM + n] =
                make_float2(acc[i][nj][2], acc[i][nj][3]);
        }
    }
}

// ---------------------------------------------------------------------------
// Tensor-core flash attention, bf16 hi/lo; bias bf16; writes O hi/lo.
// ---------------------------------------------------------------------------
#define AROWB 144
#define ATILE (128 * AROWB)
#define ATT_SMEM (2 * ATILE + 2 * 4 * ATILE)
#define LOG2E 1.4426950408889634f

__device__ __forceinline__ void a_load_stage(
    uint32_t st, const __nv_bfloat16* __restrict__ Kh, const __nv_bfloat16* __restrict__ Kl,
    const __nv_bfloat16* __restrict__ Vh, const __nv_bfloat16* __restrict__ Vl,
    int k0, int tid)
{
#pragma unroll
    for (int i = 0; i < 4; i++) {
        int q = tid + i * 256;
        int row = q >> 3, cc = q & 7;
        uint32_t so = row * AROWB + cc * 16;
        size_t g = (size_t)(k0 + row) * HD_DIM + cc * 8;
        cp16(st + so,             Kh + g);
        cp16(st + ATILE + so,     Kl + g);
        cp16(st + 2 * ATILE + so, Vh + g);
        cp16(st + 3 * ATILE + so, Vl + g);
    }
}

__global__ __launch_bounds__(256, 1) void attn_tc_kernel(
    const float* __restrict__ modw, const float* __restrict__ temps)
{
    extern __shared__ char smem[];
    const uint32_t sb = s2u(smem);
    const uint32_t sQh = sb, sQl = sb + ATILE;
    const uint32_t sStage = sb + 2 * ATILE;

    const int tid  = threadIdx.x;
    const int w    = tid >> 5;
    const int lane = tid & 31;
    const int qb = gridDim.x - 1 - blockIdx.x;
    const int h  = blockIdx.y;
    const int q0 = qb * 128;

    const float wgt = modw[c_h2m[h]];
    const float A1  = 0.125f * temps[h] * wgt * LOG2E;
    const float B1  = wgt * LOG2E;

    const __nv_bfloat16* Qhg = g_Qh + ((size_t)h * T_DIM + q0) * HD_DIM;
    const __nv_bfloat16* Qlg = g_Ql + ((size_t)h * T_DIM + q0) * HD_DIM;
    const __nv_bfloat16* Khg = g_Kh + (size_t)h * T_DIM * HD_DIM;
    const __nv_bfloat16* Klg = g_Kl + (size_t)h * T_DIM * HD_DIM;
    const __nv_bfloat16* Vhg = g_Vh + (size_t)h * T_DIM * HD_DIM;
    const __nv_bfloat16* Vlg = g_Vl + (size_t)h * T_DIM * HD_DIM;

#pragma unroll
    for (int i = 0; i < 4; i++) {
        int q = tid + i * 256;
        int row = q >> 3, cc = q & 7;
        uint32_t so = row * AROWB + cc * 16;
        size_t g = (size_t)row * HD_DIM + cc * 8;
        cp16(sQh + so, Qhg + g);
        cp16(sQl + so, Qlg + g);
    }
    a_load_stage(sStage, Khg, Klg, Vhg, Vlg, 0, tid);
    cp_commit();
    if (qb >= 1) a_load_stage(sStage + 4 * ATILE, Khg, Klg, Vhg, Vlg, 128, tid);
    cp_commit();

    const int wq  = w * 16;
    const int lm  = lane & 15;
    const uint32_t kboff = (uint32_t)(lane >> 4) * 16;
    const int r   = lane >> 2;
    const int c2  = (lane & 3) * 2;
    const int qr0 = q0 + wq + r;
    const int qr1 = qr0 + 8;

    float m0 = -1e30f, m1 = -1e30f, l0 = 0.f, l1 = 0.f;
    float o[8][4];
#pragma unroll
    for (int j = 0; j < 8; j++)
#pragma unroll
        for (int q = 0; q < 4; q++) o[j][q] = 0.f;

    const uint32_t aQh = sQh + (uint32_t)(wq + lm) * AROWB + kboff;
    const uint32_t aQl = sQl + (uint32_t)(wq + lm) * AROWB + kboff;

    for (int kb = 0; kb <= qb; kb++) {
        cp_wait1();
        __syncthreads();
        const uint32_t st = sStage + (uint32_t)(kb & 1) * 4 * ATILE;
        const bool diag = (kb == qb);
        const int k0 = kb * 128;

        float s[16][4];
#pragma unroll
        for (int j = 0; j < 16; j++)
#pragma unroll
            for (int q = 0; q < 4; q++) s[j][q] = 0.f;

#pragma unroll
        for (int ks = 0; ks < 4; ks++) {
            const uint32_t ko = (uint32_t)ks * 32;
            uint32_t ah[4], al[4];
            ldm_x4(ah, aQh + ko);
            ldm_x4(al, aQl + ko);
#pragma unroll
            for (int ng = 0; ng < 8; ng++) {
                uint32_t bh[4], bl[4];
                const uint32_t aK = st + (uint32_t)(ng * 16 + lm) * AROWB + kboff + ko;
                ldm_x4(bh, aK);
                ldm_x4(bl, aK + ATILE);
                mma16816(s[2 * ng],     ah, bh[0], bh[2]);
                mma16816(s[2 * ng + 1], ah, bh[1], bh[3]);
                mma16816(s[2 * ng],     ah, bl[0], bl[2]);
                mma16816(s[2 * ng + 1], ah, bl[1], bl[3]);
                mma16816(s[2 * ng],     al, bh[0], bh[2]);
                mma16816(s[2 * ng + 1], al, bh[1], bh[3]);
            }
        }

        const __nv_bfloat16* br0 = g_cb + (size_t)qr0 * T_DIM + k0;
        const __nv_bfloat16* br1 = g_cb + (size_t)qr1 * T_DIM + k0;
        float vmax0 = -1e30f, vmax1 = -1e30f;
#pragma unroll
        for (int j = 0; j < 16; j++) {
            const int kc = j * 8 + c2;
            float2 b0 = __bfloat1622float2(*(const __nv_bfloat162*)(br0 + kc));
            float2 b1 = __bfloat1622float2(*(const __nv_bfloat162*)(br1 + kc));
            s[j][0] = s[j][0] * A1 + b0.x * B1;
            s[j][1] = s[j][1] * A1 + b0.y * B1;
            s[j][2] = s[j][2] * A1 + b1.x * B1;
            s[j][3] = s[j][3] * A1 + b1.y * B1;
            if (diag) {
                const int ka = k0 + kc;
                if (ka > qr0)     s[j][0] = -1e30f;
                if (ka + 1 > qr0) s[j][1] = -1e30f;
                if (ka > qr1)     s[j][2] = -1e30f;
                if (ka + 1 > qr1) s[j][3] = -1e30f;
            }
            vmax0 = fmaxf(vmax0, fmaxf(s[j][0], s[j][1]));
            vmax1 = fmaxf(vmax1, fmaxf(s[j][2], s[j][3]));
        }
        vmax0 = fmaxf(vmax0, __shfl_xor_sync(0xffffffffu, vmax0, 1));
        vmax0 = fmaxf(vmax0, __shfl_xor_sync(0xffffffffu, vmax0, 2));
        vmax1 = fmaxf(vmax1, __shfl_xor_sync(0xffffffffu, vmax1, 1));
        vmax1 = fmaxf(vmax1, __shfl_xor_sync(0xffffffffu, vmax1, 2));

        const float mn0 = fmaxf(m0, vmax0);
        const float mn1 = fmaxf(m1, vmax1);
        const float al0 = ex2(m0 - mn0);
        const float al1 = ex2(m1 - mn1);
        m0 = mn0; m1 = mn1;

        float rs0 = 0.f, rs1 = 0.f;
#pragma unroll
        for (int j = 0; j < 16; j++) {
            s[j][0] = ex2(s[j][0] - mn0);
            s[j][1] = ex2(s[j][1] - mn0);
            s[j][2] = ex2(s[j][2] - mn1);
            s[j][3] = ex2(s[j][3] - mn1);
            rs0 += s[j][0] + s[j][1];
            rs1 += s[j][2] + s[j][3];
        }
        rs0 += __shfl_xor_sync(0xffffffffu, rs0, 1);
        rs0 += __shfl_xor_sync(0xffffffffu, rs0, 2);
        rs1 += __shfl_xor_sync(0xffffffffu, rs1, 1);
        rs1 += __shfl_xor_sync(0xffffffffu, rs1, 2);
        l0 = l0 * al0 + rs0;
        l1 = l1 * al1 + rs1;

#pragma unroll
        for (int j = 0; j < 8; j++) {
            o[j][0] *= al0; o[j][1] *= al0;
            o[j][2] *= al1; o[j][3] *= al1;
        }

#pragma unroll
        for (int ks = 0; ks < 8; ks++) {
            uint32_t ph[4], pl[4];
#pragma unroll
            for (int u = 0; u < 2; u++) {
                const int j = 2 * ks + u;
                uint32_t d0 = pack_bf2(s[j][0], s[j][1]);
                uint32_t d1 = pack_bf2(s[j][2], s[j][3]);
                ph[u]     = d0;  ph[2 + u] = d1;
                pl[u]     = pack_bf2(s[j][0] - bf_lo(d0), s[j][1] - bf_hi(d0));
                pl[2 + u] = pack_bf2(s[j][2] - bf_lo(d1), s[j][3] - bf_hi(d1));
            }
            uint32_t pa_h[4] = { ph[0], ph[2], ph[1], ph[3] };
            uint32_t pa_l[4] = { pl[0], pl[2], pl[1], pl[3] };
#pragma unroll
            for (int nv = 0; nv < 2; nv++) {
#pragma unroll
                for (int half = 0; half < 2; half++) {
                    const int n0 = nv * 32 + half * 16;
                    const uint32_t aV = st + 2 * ATILE
                        + (uint32_t)(ks * 16 + lm) * AROWB
                        + (uint32_t)(n0 + ((lane >> 4) * 8)) * 2;
                    uint32_t vh[4], vl[4];
                    ldm_x4_t(vh, aV);
                    ldm_x4_t(vl, aV + ATILE);
                    const int jt = nv * 4 + half * 2;
                    mma16816(o[jt],     pa_h, vh[0], vh[1]);
                    mma16816(o[jt + 1], pa_h, vh[2], vh[3]);
                    mma16816(o[jt],     pa_h, vl[0], vl[1]);
                    mma16816(o[jt + 1], pa_h, vl[2], vl[3]);
                    mma16816(o[jt],     pa_l, vh[0], vh[1]);
                    mma16816(o[jt + 1], pa_l, vh[2], vh[3]);
                }
            }
        }

        __syncthreads();
        if (kb + 2 <= qb)
            a_load_stage(sStage + (uint32_t)(kb & 1) * 4 * ATILE,
                         Khg, Klg, Vhg, Vlg, (kb + 2) * 128, tid);
        cp_commit();
    }

    // epilogue: normalize, hi/lo split, write bf16 [T][D]
    const float inv0 = 1.f / l0, inv1 = 1.f / l1;
#pragma unroll
    for (int j = 0; j < 8; j++) {
        const int d = j * 8 + c2;
        float a0 = o[j][0] * inv0, a1 = o[j][1] * inv0;
        float b0 = o[j][2] * inv1, b1 = o[j][3] * inv1;
        uint32_t h0 = pack_bf2(a0, a1);
        uint32_t h1 = pack_bf2(b0, b1);
        uint32_t lo0 = pack_bf2(a0 - bf_lo(h0), a1 - bf_hi(h0));
        uint32_t lo1 = pack_bf2(b0 - bf_lo(h1), b1 - bf_hi(h1));
        size_t i0 = (size_t)qr0 * D_DIM + h * HD_DIM + d;
        size_t i1 = (size_t)qr1 * D_DIM + h * HD_DIM + d;
        *(uint32_t*)&g_oh[i0] = h0;  *(uint32_t*)&g_ol[i0] = lo0;
        *(uint32_t*)&g_oh[i1] = h1;  *(uint32_t*)&g_ol[i1] = lo1;
    }
}

// ---------------------------------------------------------------------------
extern "C" void kernel_launch(void* const* d_in, const int* in_sizes, int n_in,
                              void* d_out, int out_size)
{
    const float* x  = (const float*)d_in[0];
    const float* cb = (const float*)d_in[2];
    const float* mw = (const float*)d_in[3];
    const float* Wq = (const float*)d_in[4];
    const float* Wk = (const float*)d_in[5];
    const float* Wv = (const float*)d_in[6];
    const float* Wo = (const float*)d_in[7];
    const float* ts = (const float*)d_in[8];
    float* out = (float*)d_out;

    cudaFuncSetAttribute(gemm_qkv_kernel,
                         cudaFuncAttributeMaxDynamicSharedMemorySize, GEMM_SMEM);
    cudaFuncSetAttribute(gemm_out_kernel,
                         cudaFuncAttributeMaxDynamicSharedMemorySize, GEMM_SMEM);
    cudaFuncSetAttribute(attn_tc_kernel,
                         cudaFuncAttributeMaxDynamicSharedMemorySize, ATT_SMEM);

    // Launch order keeps gemm_qkv_kernel in the profiled launch slot.
    splitA_kernel<<<dim3(4096, 3), 256>>>((const float4*)x, (const float4*)Wq,
                                          (const float4*)Wk);
    splitB_kernel<<<dim3(4096, 2), 256>>>((const float4*)Wv, (const float4*)Wo);
    bias_bf16_kernel<<<8192, 256>>>((const float2*)cb);

    gemm_qkv_kernel<<<dim3(16, 16, 3), 256, GEMM_SMEM>>>();

    rope_split_kernel<<<(H_NUM * T_DIM * 32) / 256, 256>>>();

    attn_tc_kernel<<<dim3(T_DIM / 128, H_NUM), 256, ATT_SMEM>>>(mw, ts);

    gemm_out_kernel<<<dim3(16, 16), 256, GEMM_SMEM>>>(out);
}

// round 11
// speedup vs baseline: 1.0500x; 1.0031x over previous
#include <cuda_runtime.h>
#include <cuda_bf16.h>
#include <math.h>
#include <stdint.h>

#define T_DIM 2048
#define D_DIM 2048
#define H_NUM 32
#define HD_DIM 64

// ---------------------------------------------------------------------------
// Scratch (__device__ globals; allocation-free rule)
// ---------------------------------------------------------------------------
__device__ float g_Q[H_NUM * T_DIM * HD_DIM];   // [H][T][64] fp32 (pre-RoPE)
__device__ float g_K[H_NUM * T_DIM * HD_DIM];

__device__ __nv_bfloat16 g_xh[D_DIM * D_DIM],  g_xl[D_DIM * D_DIM];
__device__ __nv_bfloat16 g_wqh[D_DIM * D_DIM], g_wql[D_DIM * D_DIM];
__device__ __nv_bfloat16 g_wkh[D_DIM * D_DIM], g_wkl[D_DIM * D_DIM];
__device__ __nv_bfloat16 g_wvh[D_DIM * D_DIM], g_wvl[D_DIM * D_DIM];
__device__ __nv_bfloat16 g_woh[D_DIM * D_DIM], g_wol[D_DIM * D_DIM];
__device__ __nv_bfloat16 g_oh[D_DIM * D_DIM],  g_ol[D_DIM * D_DIM];  // attn out hi/lo [T][D]
// RoPE'd Q/K and V, bf16 hi/lo, [H][T][64]
__device__ __nv_bfloat16 g_Qh[H_NUM * T_DIM * HD_DIM], g_Ql[H_NUM * T_DIM * HD_DIM];
__device__ __nv_bfloat16 g_Kh[H_NUM * T_DIM * HD_DIM], g_Kl[H_NUM * T_DIM * HD_DIM];
__device__ __nv_bfloat16 g_Vh[H_NUM * T_DIM * HD_DIM], g_Vl[H_NUM * T_DIM * HD_DIM];
__device__ __nv_bfloat16 g_cb[T_DIM * T_DIM];   // context bias, bf16

// head -> module index, HEAD_COUNTS = {8,6,4,4,6,4}
__constant__ int c_h2m[H_NUM] = {0,0,0,0,0,0,0,0,
                                 1,1,1,1,1,1,
                                 2,2,2,2,
                                 3,3,3,3,
                                 4,4,4,4,4,4,
                                 5,5,5,5};

// ---------------------------------------------------------------------------
// PTX helpers (sm_100-safe: cp.async / ldmatrix / mma.sync)
// ---------------------------------------------------------------------------
__device__ __forceinline__ uint32_t s2u(const void* p) {
    uint32_t a;
    asm("{ .reg .u64 t; cvta.to.shared.u64 t, %1; cvt.u32.u64 %0, t; }"
        : "=r"(a) : "l"(p));
    return a;
}
__device__ __forceinline__ void cp16(uint32_t d, const void* s) {
    asm volatile("cp.async.cg.shared.global [%0], [%1], 16;" :: "r"(d), "l"(s));
}
__device__ __forceinline__ void cp_commit() {
    asm volatile("cp.async.commit_group;" ::: "memory");
}
__device__ __forceinline__ void cp_wait0() {
    asm volatile("cp.async.wait_group 0;" ::: "memory");
}
__device__ __forceinline__ void cp_wait1() {
    asm volatile("cp.async.wait_group 1;" ::: "memory");
}
__device__ __forceinline__ void ldm_x4(uint32_t* r, uint32_t a) {
    asm volatile("ldmatrix.sync.aligned.m8n8.x4.shared.b16 {%0,%1,%2,%3}, [%4];"
                 : "=r"(r[0]), "=r"(r[1]), "=r"(r[2]), "=r"(r[3]) : "r"(a));
}
__device__ __forceinline__ void ldm_x4_t(uint32_t* r, uint32_t a) {
    asm volatile("ldmatrix.sync.aligned.m8n8.x4.trans.shared.b16 {%0,%1,%2,%3}, [%4];"
                 : "=r"(r[0]), "=r"(r[1]), "=r"(r[2]), "=r"(r[3]) : "r"(a));
}
__device__ __forceinline__ void mma16816(float* d, const uint32_t* a,
                                         uint32_t b0, uint32_t b1) {
    asm volatile("mma.sync.aligned.m16n8k16.row.col.f32.bf16.bf16.f32 "
        "{%0,%1,%2,%3},{%4,%5,%6,%7},{%8,%9},{%0,%1,%2,%3};"
        : "+f"(d[0]), "+f"(d[1]), "+f"(d[2]), "+f"(d[3])
        : "r"(a[0]), "r"(a[1]), "r"(a[2]), "r"(a[3]), "r"(b0), "r"(b1));
}
__device__ __forceinline__ float ex2(float x) {
    float r;
    asm("ex2.approx.f32 %0, %1;" : "=f"(r) : "f"(x));
    return r;
}
__device__ __forceinline__ uint32_t pack_bf2(float a, float b) {
    uint32_t r;
    asm("cvt.rn.bf16x2.f32 %0, %1, %2;" : "=r"(r) : "f"(b), "f"(a));
    return r;
}
__device__ __forceinline__ float bf_lo(uint32_t v) { return __uint_as_float(v << 16); }
__device__ __forceinline__ float bf_hi(uint32_t v) { return __uint_as_float(v & 0xFFFF0000u); }

// ---------------------------------------------------------------------------
// fp32 -> bf16 hi/lo splits for input matrices
// ---------------------------------------------------------------------------
__device__ __forceinline__ void split_one(const float4* __restrict__ src,
                                          __nv_bfloat162* __restrict__ hi,
                                          __nv_bfloat162* __restrict__ lo, int i)
{
    float4 v = src[i];
    __nv_bfloat16 h0 = __float2bfloat16(v.x), h1 = __float2bfloat16(v.y);
    __nv_bfloat16 h2 = __float2bfloat16(v.z), h3 = __float2bfloat16(v.w);
    float l0 = v.x - __bfloat162float(h0), l1 = v.y - __bfloat162float(h1);
    float l2 = v.z - __bfloat162float(h2), l3 = v.w - __bfloat162float(h3);
    hi[2 * i]     = __halves2bfloat162(h0, h1);
    hi[2 * i + 1] = __halves2bfloat162(h2, h3);
    lo[2 * i]     = __halves2bfloat162(__float2bfloat16(l0), __float2bfloat16(l1));
    lo[2 * i + 1] = __halves2bfloat162(__float2bfloat16(l2), __float2bfloat16(l3));
}

__global__ __launch_bounds__(256) void splitA_kernel(
    const float4* __restrict__ s0, const float4* __restrict__ s1,
    const float4* __restrict__ s2)
{
    const int y = blockIdx.y;
    const float4* src = y == 0 ? s0 : y == 1 ? s1 : s2;
    __nv_bfloat162* hi = (__nv_bfloat162*)(y == 0 ? g_xh : y == 1 ? g_wqh : g_wkh);
    __nv_bfloat162* lo = (__nv_bfloat162*)(y == 0 ? g_xl : y == 1 ? g_wql : g_wkl);
    split_one(src, hi, lo, blockIdx.x * 256 + threadIdx.x);
}

__global__ __launch_bounds__(256) void splitB_kernel(
    const float4* __restrict__ s0, const float4* __restrict__ s1)
{
    const int y = blockIdx.y;
    const float4* src = y == 0 ? s0 : s1;
    __nv_bfloat162* hi = (__nv_bfloat162*)(y == 0 ? g_wvh : g_woh);
    __nv_bfloat162* lo = (__nv_bfloat162*)(y == 0 ? g_wvl : g_wol);
    split_one(src, hi, lo, blockIdx.x * 256 + threadIdx.x);
}

// context bias fp32 -> bf16
__global__ __launch_bounds__(256) void bias_bf16_kernel(const float2* __restrict__ cb)
{
    int i = blockIdx.x * 256 + threadIdx.x;
    float2 v = cb[i];
    ((__nv_bfloat162*)g_cb)[i] = __halves2bfloat162(__float2bfloat16(v.x),
                                                    __float2bfloat16(v.y));
}

// ---------------------------------------------------------------------------
// RoPE + hi/lo split for Q,K
// ---------------------------------------------------------------------------
__global__ __launch_bounds__(256) void rope_split_kernel()
{
    int idx = blockIdx.x * 256 + threadIdx.x;
    int i = idx & 31;
    int t = (idx >> 5) & (T_DIM - 1);
    int h = idx >> 16;

    float f = exp2f(-(float)i * 0.41524101186092030f);   // 10000^(-i/32)
    float ang = (float)t * f;
    float c = cosf(ang), s = sinf(ang);

    size_t base = ((size_t)h * T_DIM + t) * HD_DIM + i;
    float q1 = g_Q[base], q2 = g_Q[base + 32];
    float qa = q1 * c - q2 * s;
    float qb = q2 * c + q1 * s;
    float k1 = g_K[base], k2 = g_K[base + 32];
    float ka = k1 * c - k2 * s;
    float kb = k2 * c + k1 * s;

    __nv_bfloat16 hqa = __float2bfloat16(qa), hqb = __float2bfloat16(qb);
    __nv_bfloat16 hka = __float2bfloat16(ka), hkb = __float2bfloat16(kb);
    g_Qh[base]      = hqa; g_Ql[base]      = __float2bfloat16(qa - __bfloat162float(hqa));
    g_Qh[base + 32] = hqb; g_Ql[base + 32] = __float2bfloat16(qb - __bfloat162float(hqb));
    g_Kh[base]      = hka; g_Kl[base]      = __float2bfloat16(ka - __bfloat162float(hka));
    g_Kh[base + 32] = hkb; g_Kl[base + 32] = __float2bfloat16(kb - __bfloat162float(hkb));
}

// ---------------------------------------------------------------------------
// GEMM core (CTA 128x128, BK=32, 2-stage cp.async double buffer,
// 2 CTAs/SM, bf16 hi/lo 3-pass)  — unchanged from round 9
// ---------------------------------------------------------------------------
#define ROWB      80
#define ARR_BYTES (128 * ROWB)
#define STG_BYTES (4 * ARR_BYTES)       // 40960
#define GEMM_SMEM (2 * STG_BYTES)       // 80 KB -> 2 CTAs/SM

__device__ __forceinline__ void g_load_stage(
    uint32_t st, const __nv_bfloat16* __restrict__ Ah, const __nv_bfloat16* __restrict__ Al,
    const __nv_bfloat16* __restrict__ Bh, const __nv_bfloat16* __restrict__ Bl,
    int t0, int o0, int k0, int tid)
{
    const int r = tid >> 2;
    const int c = (tid & 3);
    const int e = c * 8;
#pragma unroll
    for (int half = 0; half < 2; half++) {
        int row = r + half * 64;
        uint32_t so = row * ROWB + c * 16;
        size_t ga = (size_t)(t0 + row) * D_DIM + k0 + e;
        size_t gb = (size_t)(o0 + row) * D_DIM + k0 + e;
        cp16(st + so,                 Ah + ga);
        cp16(st + ARR_BYTES + so,     Al + ga);
        cp16(st + 2 * ARR_BYTES + so, Bh + gb);
        cp16(st + 3 * ARR_BYTES + so, Bl + gb);
    }
    cp_commit();
}

__device__ __forceinline__ void gemm_mainloop(
    uint32_t sb, const __nv_bfloat16* Ah, const __nv_bfloat16* Al,
    const __nv_bfloat16* Bh, const __nv_bfloat16* Bl,
    int t0, int o0, int tid, float acc[4][4][4])
{
    const int w    = tid >> 5;
    const int lane = tid & 31;
    const int wm0 = (w >> 2) * 64;
    const int wn0 = (w & 3) * 32;

#pragma unroll
    for (int i = 0; i < 4; i++)
#pragma unroll
        for (int j = 0; j < 4; j++)
#pragma unroll
            for (int q = 0; q < 4; q++) acc[i][j][q] = 0.f;

    g_load_stage(sb, Ah, Al, Bh, Bl, t0, o0, 0, tid);

    const int lm = lane & 15;
    const uint32_t kb = (uint32_t)(lane >> 4) * 16;

    for (int it = 0; it < 64; it++) {
        __syncthreads();                 // compute(it-1) done by all warps
        if (it + 1 < 64) {
            g_load_stage(sb + (uint32_t)((it + 1) & 1) * STG_BYTES,
                         Ah, Al, Bh, Bl, t0, o0, (it + 1) * 32, tid);
            cp_wait1();                  // stage it complete, it+1 in flight
        } else {
            cp_wait0();                  // last stage complete
        }
        __syncthreads();                 // stage it visible to all warps

        const uint32_t st = sb + (uint32_t)(it & 1) * STG_BYTES;
        const uint32_t aA = st + (uint32_t)(wm0 + lm) * ROWB + kb;
        const uint32_t aB = st + 2u * ARR_BYTES + (uint32_t)(wn0 + lm) * ROWB + kb;

#pragma unroll
        for (int ks = 0; ks < 2; ks++) {
            const uint32_t ko = (uint32_t)ks * 32;
            uint32_t ah[4][4], al[4][4], bh[2][4], bl[2][4];
#pragma unroll
            for (int i = 0; i < 4; i++) {
                ldm_x4(ah[i], aA + (uint32_t)(i * 16) * ROWB + ko);
                ldm_x4(al[i], aA + ARR_BYTES + (uint32_t)(i * 16) * ROWB + ko);
            }
#pragma unroll
            for (int j = 0; j < 2; j++) {
                ldm_x4(bh[j], aB + (uint32_t)(j * 16) * ROWB + ko);
                ldm_x4(bl[j], aB + ARR_BYTES + (uint32_t)(j * 16) * ROWB + ko);
            }
#pragma unroll
            for (int i = 0; i < 4; i++) {
#pragma unroll
                for (int nj = 0; nj < 4; nj++) {
                    const int g = nj >> 1, o = nj & 1;
                    mma16816(acc[i][nj], ah[i], bh[g][o], bh[g][2 + o]);
                    mma16816(acc[i][nj], ah[i], bl[g][o], bl[g][2 + o]);
                    mma16816(acc[i][nj], al[i], bh[g][o], bh[g][2 + o]);
                }
            }
        }
    }
    __syncthreads();
}

// QKV projections, one launch. z=0: Q, z=1: K (fp32 head layout),
// z=2: V (bf16 hi/lo head layout).
__global__ __launch_bounds__(256, 2) void gemm_qkv_kernel()
{
    extern __shared__ char smem[];
    const uint32_t sb = s2u(smem);
    const int tid = threadIdx.x;
    const int t0 = blockIdx.x * 128;
    const int o0 = blockIdx.y * 128;
    const int z  = blockIdx.z;

    const __nv_bfloat16* Bh = z == 0 ? g_wqh : z == 1 ? g_wkh : g_wvh;
    const __nv_bfloat16* Bl = z == 0 ? g_wql : z == 1 ? g_wkl : g_wvl;

    float acc[4][4][4];
    gemm_mainloop(sb, g_xh, g_xl, Bh, Bl, t0, o0, tid, acc);

    const int lane = tid & 31;
    const int w = tid >> 5;
    const int wm0 = (w >> 2) * 64, wn0 = (w & 3) * 32;
    const int tr = lane >> 2, tc = (lane & 3) * 2;
#pragma unroll
    for (int i = 0; i < 4; i++) {
#pragma unroll
        for (int nj = 0; nj < 4; nj++) {
            const int m0 = t0 + wm0 + i * 16 + tr;
            const int n  = o0 + wn0 + nj * 8 + tc;
            float2 v0 = make_float2(acc[i][nj][0], acc[i][nj][1]);
            float2 v1 = make_float2(acc[i][nj][2], acc[i][nj][3]);
            size_t base = ((size_t)(n >> 6) * T_DIM) * HD_DIM + (n & 63);
            if (z < 2) {
                float* C = z == 0 ? g_Q : g_K;
                *(float2*)&C[base + (size_t)m0 * HD_DIM]       = v0;
                *(float2*)&C[base + (size_t)(m0 + 8) * HD_DIM] = v1;
            } else {
                uint32_t h0 = pack_bf2(v0.x, v0.y);
                uint32_t h1 = pack_bf2(v1.x, v1.y);
                uint32_t l0 = pack_bf2(v0.x - bf_lo(h0), v0.y - bf_hi(h0));
                uint32_t l1 = pack_bf2(v1.x - bf_lo(h1), v1.y - bf_hi(h1));
                *(uint32_t*)&g_Vh[base + (size_t)m0 * HD_DIM]       = h0;
                *(uint32_t*)&g_Vh[base + (size_t)(m0 + 8) * HD_DIM] = h1;
                *(uint32_t*)&g_Vl[base + (size_t)m0 * HD_DIM]       = l0;
                *(uint32_t*)&g_Vl[base + (size_t)(m0 + 8) * HD_DIM] = l1;
            }
        }
    }
}

// Output projection: out = O * Wo^T, O given as hi/lo bf16 [T][D]
__global__ __launch_bounds__(256, 2) void gemm_out_kernel(float* __restrict__ C)
{
    extern __shared__ char smem[];
    const uint32_t sb = s2u(smem);
    const int tid = threadIdx.x;
    const int t0 = blockIdx.x * 128;
    const int o0 = blockIdx.y * 128;

    float acc[4][4][4];
    gemm_mainloop(sb, g_oh, g_ol, g_woh, g_wol, t0, o0, tid, acc);

    const int lane = tid & 31;
    const int w = tid >> 5;
    const int wm0 = (w >> 2) * 64, wn0 = (w & 3) * 32;
    const int tr = lane >> 2, tc = (lane & 3) * 2;
#pragma unroll
    for (int i = 0; i < 4; i++) {
#pragma unroll
        for (int nj = 0; nj < 4; nj++) {
            const int m0 = t0 + wm0 + i * 16 + tr;
            const int n  = o0 + wn0 + nj * 8 + tc;
            *(float2*)&C[(size_t)m0 * D_DIM + n] =
                make_float2(acc[i][nj][0], acc[i][nj][1]);
            *(float2*)&C[(size_t)(m0 + 8) * D_DIM + n] =
                make_float2(acc[i][nj][2], acc[i][nj][3]);
        }
    }
}

// ---------------------------------------------------------------------------
// Tensor-core flash attention, bf16 hi/lo; 64-row K/V stages -> 110.6 KB smem
// -> 2 CTAs/SM (occupancy fix, same lever that worked on the GEMM).
// ---------------------------------------------------------------------------
#define AROWB   144
#define ATILE_Q (128 * AROWB)           // 18432 (Q hi or lo)
#define KTILE   (64 * AROWB)            // 9216 (one 64-row array)
#define ASTG    (4 * KTILE)             // 36864 (Kh,Kl,Vh,Vl per stage)
#define ATT_SMEM (2 * ATILE_Q + 2 * ASTG)   // 110592 B
#define LOG2E 1.4426950408889634f

// Load one 64-row K/V stage (Kh,Kl,Vh,Vl), 8 cp16 per thread.
__device__ __forceinline__ void a_load_stage64(
    uint32_t st, const __nv_bfloat16* __restrict__ Kh, const __nv_bfloat16* __restrict__ Kl,
    const __nv_bfloat16* __restrict__ Vh, const __nv_bfloat16* __restrict__ Vl,
    int k0, int tid)
{
#pragma unroll
    for (int i = 0; i < 2; i++) {
        int q = tid + i * 256;          // 0..511
        int row = q >> 3, cc = q & 7;
        uint32_t so = row * AROWB + cc * 16;
        size_t g = (size_t)(k0 + row) * HD_DIM + cc * 8;
        cp16(st + so,             Kh + g);
        cp16(st + KTILE + so,     Kl + g);
        cp16(st + 2 * KTILE + so, Vh + g);
        cp16(st + 3 * KTILE + so, Vl + g);
    }
}

__global__ __launch_bounds__(256, 2) void attn_tc_kernel(
    const float* __restrict__ modw, const float* __restrict__ temps)
{
    extern __shared__ char smem[];
    const uint32_t sb = s2u(smem);
    const uint32_t sQh = sb, sQl = sb + ATILE_Q;
    const uint32_t sStage = sb + 2 * ATILE_Q;

    const int tid  = threadIdx.x;
    const int w    = tid >> 5;
    const int lane = tid & 31;
    const int qb = gridDim.x - 1 - blockIdx.x;   // heavy tiles first
    const int h  = blockIdx.y;
    const int q0 = qb * 128;

    const float wgt = modw[c_h2m[h]];
    const float A1  = 0.125f * temps[h] * wgt * LOG2E;
    const float B1  = wgt * LOG2E;

    const __nv_bfloat16* Qhg = g_Qh + ((size_t)h * T_DIM + q0) * HD_DIM;
    const __nv_bfloat16* Qlg = g_Ql + ((size_t)h * T_DIM + q0) * HD_DIM;
    const __nv_bfloat16* Khg = g_Kh + (size_t)h * T_DIM * HD_DIM;
    const __nv_bfloat16* Klg = g_Kl + (size_t)h * T_DIM * HD_DIM;
    const __nv_bfloat16* Vhg = g_Vh + (size_t)h * T_DIM * HD_DIM;
    const __nv_bfloat16* Vlg = g_Vl + (size_t)h * T_DIM * HD_DIM;

    // Prologue: Q tile + stages 0,1
#pragma unroll
    for (int i = 0; i < 4; i++) {
        int q = tid + i * 256;
        int row = q >> 3, cc = q & 7;
        uint32_t so = row * AROWB + cc * 16;
        size_t g = (size_t)row * HD_DIM + cc * 8;
        cp16(sQh + so, Qhg + g);
        cp16(sQl + so, Qlg + g);
    }
    a_load_stage64(sStage, Khg, Klg, Vhg, Vlg, 0, tid);
    cp_commit();
    a_load_stage64(sStage + ASTG, Khg, Klg, Vhg, Vlg, 64, tid);
    cp_commit();

    const int wq  = w * 16;
    const int lm  = lane & 15;
    const uint32_t kboff = (uint32_t)(lane >> 4) * 16;
    const int r   = lane >> 2;
    const int c2  = (lane & 3) * 2;
    const int qr0 = q0 + wq + r;
    const int qr1 = qr0 + 8;

    float m0 = -1e30f, m1 = -1e30f, l0 = 0.f, l1 = 0.f;
    float o[8][4];
#pragma unroll
    for (int j = 0; j < 8; j++)
#pragma unroll
        for (int q = 0; q < 4; q++) o[j][q] = 0.f;

    const uint32_t aQh = sQh + (uint32_t)(wq + lm) * AROWB + kboff;
    const uint32_t aQl = sQl + (uint32_t)(wq + lm) * AROWB + kboff;

    const int nkb = 2 * qb + 2;        // 64-row K blocks covering [0, q0+128)

    for (int kb = 0; kb < nkb; kb++) {
        cp_wait1();
        __syncthreads();
        const uint32_t st = sStage + (uint32_t)(kb & 1) * ASTG;
        const bool diag = (kb >= nkb - 2);   // only last two blocks may mask
        const int k0 = kb * 64;

        // ---- S = Q K^T over a 128x64 tile (hi/lo, 3 passes) ----
        float s[8][4];
#pragma unroll
        for (int j = 0; j < 8; j++)
#pragma unroll
            for (int q = 0; q < 4; q++) s[j][q] = 0.f;

#pragma unroll
        for (int ks = 0; ks < 4; ks++) {
            const uint32_t ko = (uint32_t)ks * 32;
            uint32_t ah[4], al[4];
            ldm_x4(ah, aQh + ko);
            ldm_x4(al, aQl + ko);
#pragma unroll
            for (int ng = 0; ng < 4; ng++) {
                uint32_t bh[4], bl[4];
                const uint32_t aK = st + (uint32_t)(ng * 16 + lm) * AROWB + kboff + ko;
                ldm_x4(bh, aK);
                ldm_x4(bl, aK + KTILE);
                mma16816(s[2 * ng],     ah, bh[0], bh[2]);
                mma16816(s[2 * ng + 1], ah, bh[1], bh[3]);
                mma16816(s[2 * ng],     ah, bl[0], bl[2]);
                mma16816(s[2 * ng + 1], ah, bl[1], bl[3]);
                mma16816(s[2 * ng],     al, bh[0], bh[2]);
                mma16816(s[2 * ng + 1], al, bh[1], bh[3]);
            }
        }

        // ---- bias + scale + mask (log2 domain) ----
        const __nv_bfloat16* br0 = g_cb + (size_t)qr0 * T_DIM + k0;
        const __nv_bfloat16* br1 = g_cb + (size_t)qr1 * T_DIM + k0;
        float vmax0 = -1e30f, vmax1 = -1e30f;
#pragma unroll
        for (int j = 0; j < 8; j++) {
            const int kc = j * 8 + c2;
            float2 b0 = __bfloat1622float2(*(const __nv_bfloat162*)(br0 + kc));
            float2 b1 = __bfloat1622float2(*(const __nv_bfloat162*)(br1 + kc));
            s[j][0] = s[j][0] * A1 + b0.x * B1;
            s[j][1] = s[j][1] * A1 + b0.y * B1;
            s[j][2] = s[j][2] * A1 + b1.x * B1;
            s[j][3] = s[j][3] * A1 + b1.y * B1;
            if (diag) {
                const int ka = k0 + kc;
                if (ka > qr0)     s[j][0] = -1e30f;
                if (ka + 1 > qr0) s[j][1] = -1e30f;
                if (ka > qr1)     s[j][2] = -1e30f;
                if (ka + 1 > qr1) s[j][3] = -1e30f;
            }
            vmax0 = fmaxf(vmax0, fmaxf(s[j][0], s[j][1]));
            vmax1 = fmaxf(vmax1, fmaxf(s[j][2], s[j][3]));
        }
        vmax0 = fmaxf(vmax0, __shfl_xor_sync(0xffffffffu, vmax0, 1));
        vmax0 = fmaxf(vmax0, __shfl_xor_sync(0xffffffffu, vmax0, 2));
        vmax1 = fmaxf(vmax1, __shfl_xor_sync(0xffffffffu, vmax1, 1));
        vmax1 = fmaxf(vmax1, __shfl_xor_sync(0xffffffffu, vmax1, 2));

        const float mn0 = fmaxf(m0, vmax0);
        const float mn1 = fmaxf(m1, vmax1);
        const float al0 = ex2(m0 - mn0);
        const float al1 = ex2(m1 - mn1);
        m0 = mn0; m1 = mn1;

        float rs0 = 0.f, rs1 = 0.f;
#pragma unroll
        for (int j = 0; j < 8; j++) {
            s[j][0] = ex2(s[j][0] - mn0);
            s[j][1] = ex2(s[j][1] - mn0);
            s[j][2] = ex2(s[j][2] - mn1);
            s[j][3] = ex2(s[j][3] - mn1);
            rs0 += s[j][0] + s[j][1];
            rs1 += s[j][2] + s[j][3];
        }
        rs0 += __shfl_xor_sync(0xffffffffu, rs0, 1);
        rs0 += __shfl_xor_sync(0xffffffffu, rs0, 2);
        rs1 += __shfl_xor_sync(0xffffffffu, rs1, 1);
        rs1 += __shfl_xor_sync(0xffffffffu, rs1, 2);
        l0 = l0 * al0 + rs0;
        l1 = l1 * al1 + rs1;

#pragma unroll
        for (int j = 0; j < 8; j++) {
            o[j][0] *= al0; o[j][1] *= al0;
            o[j][2] *= al1; o[j][3] *= al1;
        }

        // ---- O += P V (hi/lo, 3 passes), 64 K rows = 4 k16 steps ----
#pragma unroll
        for (int ks = 0; ks < 4; ks++) {
            uint32_t ph[4], pl[4];
#pragma unroll
            for (int u = 0; u < 2; u++) {
                const int j = 2 * ks + u;
                uint32_t d0 = pack_bf2(s[j][0], s[j][1]);
                uint32_t d1 = pack_bf2(s[j][2], s[j][3]);
                ph[u]     = d0;  ph[2 + u] = d1;
                pl[u]     = pack_bf2(s[j][0] - bf_lo(d0), s[j][1] - bf_hi(d0));
                pl[2 + u] = pack_bf2(s[j][2] - bf_lo(d1), s[j][3] - bf_hi(d1));
            }
            uint32_t pa_h[4] = { ph[0], ph[2], ph[1], ph[3] };
            uint32_t pa_l[4] = { pl[0], pl[2], pl[1], pl[3] };
#pragma unroll
            for (int nv = 0; nv < 2; nv++) {
#pragma unroll
                for (int half = 0; half < 2; half++) {
                    const int n0 = nv * 32 + half * 16;
                    const uint32_t aV = st + 2 * KTILE
                        + (uint32_t)(ks * 16 + lm) * AROWB
                        + (uint32_t)(n0 + ((lane >> 4) * 8)) * 2;
                    uint32_t vh[4], vl[4];
                    ldm_x4_t(vh, aV);
                    ldm_x4_t(vl, aV + KTILE);
                    const int jt = nv * 4 + half * 2;
                    mma16816(o[jt],     pa_h, vh[0], vh[1]);
                    mma16816(o[jt + 1], pa_h, vh[2], vh[3]);
                    mma16816(o[jt],     pa_h, vl[0], vl[1]);
                    mma16816(o[jt + 1], pa_h, vl[2], vl[3]);
                    mma16816(o[jt],     pa_l, vh[0], vh[1]);
                    mma16816(o[jt + 1], pa_l, vh[2], vh[3]);
                }
            }
        }

        __syncthreads();   // all warps done reading stage kb
        if (kb + 2 < nkb)
            a_load_stage64(sStage + (uint32_t)(kb & 1) * ASTG,
                           Khg, Klg, Vhg, Vlg, (kb + 2) * 64, tid);
        cp_commit();
    }

    // epilogue: normalize, hi/lo split, write bf16 [T][D]
    const float inv0 = 1.f / l0, inv1 = 1.f / l1;
#pragma unroll
    for (int j = 0; j < 8; j++) {
        const int d = j * 8 + c2;
        float a0 = o[j][0] * inv0, a1 = o[j][1] * inv0;
        float b0 = o[j][2] * inv1, b1 = o[j][3] * inv1;
        uint32_t h0 = pack_bf2(a0, a1);
        uint32_t h1 = pack_bf2(b0, b1);
        uint32_t lo0 = pack_bf2(a0 - bf_lo(h0), a1 - bf_hi(h0));
        uint32_t lo1 = pack_bf2(b0 - bf_lo(h1), b1 - bf_hi(h1));
        size_t i0 = (size_t)qr0 * D_DIM + h * HD_DIM + d;
        size_t i1 = (size_t)qr1 * D_DIM + h * HD_DIM + d;
        *(uint32_t*)&g_oh[i0] = h0;  *(uint32_t*)&g_ol[i0] = lo0;
        *(uint32_t*)&g_oh[i1] = h1;  *(uint32_t*)&g_ol[i1] = lo1;
    }
}

// ---------------------------------------------------------------------------
extern "C" void kernel_launch(void* const* d_in, const int* in_sizes, int n_in,
                              void* d_out, int out_size)
{
    const float* x  = (const float*)d_in[0];
    const float* cb = (const float*)d_in[2];
    const float* mw = (const float*)d_in[3];
    const float* Wq = (const float*)d_in[4];
    const float* Wk = (const float*)d_in[5];
    const float* Wv = (const float*)d_in[6];
    const float* Wo = (const float*)d_in[7];
    const float* ts = (const float*)d_in[8];
    float* out = (float*)d_out;

    cudaFuncSetAttribute(gemm_qkv_kernel,
                         cudaFuncAttributeMaxDynamicSharedMemorySize, GEMM_SMEM);
    cudaFuncSetAttribute(gemm_out_kernel,
                         cudaFuncAttributeMaxDynamicSharedMemorySize, GEMM_SMEM);
    cudaFuncSetAttribute(attn_tc_kernel,
                         cudaFuncAttributeMaxDynamicSharedMemorySize, ATT_SMEM);

    splitA_kernel<<<dim3(4096, 3), 256>>>((const float4*)x, (const float4*)Wq,
                                          (const float4*)Wk);
    splitB_kernel<<<dim3(4096, 2), 256>>>((const float4*)Wv, (const float4*)Wo);
    bias_bf16_kernel<<<8192, 256>>>((const float2*)cb);

    gemm_qkv_kernel<<<dim3(16, 16, 3), 256, GEMM_SMEM>>>();

    rope_split_kernel<<<(H_NUM * T_DIM * 32) / 256, 256>>>();

    attn_tc_kernel<<<dim3(T_DIM / 128, H_NUM), 256, ATT_SMEM>>>(mw, ts);

    gemm_out_kernel<<<dim3(16, 16), 256, GEMM_SMEM>>>(out);
}

// round 14
// speedup vs baseline: 1.0626x; 1.0119x over previous
#include <cuda_runtime.h>
#include <cuda_bf16.h>
#include <math.h>
#include <stdint.h>

#define T_DIM 2048
#define D_DIM 2048
#define H_NUM 32
#define HD_DIM 64

// ---------------------------------------------------------------------------
// Scratch (__device__ globals; allocation-free rule)
// ---------------------------------------------------------------------------
__device__ float g_Q[H_NUM * T_DIM * HD_DIM];   // [H][T][64] fp32 (pre-RoPE)
__device__ float g_K[H_NUM * T_DIM * HD_DIM];

__device__ __nv_bfloat16 g_xh[D_DIM * D_DIM],  g_xl[D_DIM * D_DIM];
__device__ __nv_bfloat16 g_wqh[D_DIM * D_DIM], g_wql[D_DIM * D_DIM];
__device__ __nv_bfloat16 g_wkh[D_DIM * D_DIM], g_wkl[D_DIM * D_DIM];
__device__ __nv_bfloat16 g_wvh[D_DIM * D_DIM], g_wvl[D_DIM * D_DIM];
__device__ __nv_bfloat16 g_woh[D_DIM * D_DIM], g_wol[D_DIM * D_DIM];
__device__ __nv_bfloat16 g_oh[D_DIM * D_DIM],  g_ol[D_DIM * D_DIM];  // attn out hi/lo [T][D]
// RoPE'd Q/K and V, bf16 hi/lo, [H][T][64]
__device__ __nv_bfloat16 g_Qh[H_NUM * T_DIM * HD_DIM], g_Ql[H_NUM * T_DIM * HD_DIM];
__device__ __nv_bfloat16 g_Kh[H_NUM * T_DIM * HD_DIM], g_Kl[H_NUM * T_DIM * HD_DIM];
__device__ __nv_bfloat16 g_Vh[H_NUM * T_DIM * HD_DIM], g_Vl[H_NUM * T_DIM * HD_DIM];
__device__ __nv_bfloat16 g_cb[T_DIM * T_DIM];   // context bias, bf16

// head -> module index, HEAD_COUNTS = {8,6,4,4,6,4}
__constant__ int c_h2m[H_NUM] = {0,0,0,0,0,0,0,0,
                                 1,1,1,1,1,1,
                                 2,2,2,2,
                                 3,3,3,3,
                                 4,4,4,4,4,4,
                                 5,5,5,5};

// ---------------------------------------------------------------------------
// PTX helpers (sm_100-safe: cp.async / ldmatrix / mma.sync)
// ---------------------------------------------------------------------------
__device__ __forceinline__ uint32_t s2u(const void* p) {
    uint32_t a;
    asm("{ .reg .u64 t; cvta.to.shared.u64 t, %1; cvt.u32.u64 %0, t; }"
        : "=r"(a) : "l"(p));
    return a;
}
__device__ __forceinline__ void cp16(uint32_t d, const void* s) {
    asm volatile("cp.async.cg.shared.global [%0], [%1], 16;" :: "r"(d), "l"(s));
}
__device__ __forceinline__ void cp_commit() {
    asm volatile("cp.async.commit_group;" ::: "memory");
}
__device__ __forceinline__ void cp_wait0() {
    asm volatile("cp.async.wait_group 0;" ::: "memory");
}
__device__ __forceinline__ void cp_wait1() {
    asm volatile("cp.async.wait_group 1;" ::: "memory");
}
__device__ __forceinline__ void ldm_x4(uint32_t* r, uint32_t a) {
    asm volatile("ldmatrix.sync.aligned.m8n8.x4.shared.b16 {%0,%1,%2,%3}, [%4];"
                 : "=r"(r[0]), "=r"(r[1]), "=r"(r[2]), "=r"(r[3]) : "r"(a));
}
__device__ __forceinline__ void ldm_x4_t(uint32_t* r, uint32_t a) {
    asm volatile("ldmatrix.sync.aligned.m8n8.x4.trans.shared.b16 {%0,%1,%2,%3}, [%4];"
                 : "=r"(r[0]), "=r"(r[1]), "=r"(r[2]), "=r"(r[3]) : "r"(a));
}
__device__ __forceinline__ void mma16816(float* d, const uint32_t* a,
                                         uint32_t b0, uint32_t b1) {
    asm volatile("mma.sync.aligned.m16n8k16.row.col.f32.bf16.bf16.f32 "
        "{%0,%1,%2,%3},{%4,%5,%6,%7},{%8,%9},{%0,%1,%2,%3};"
        : "+f"(d[0]), "+f"(d[1]), "+f"(d[2]), "+f"(d[3])
        : "r"(a[0]), "r"(a[1]), "r"(a[2]), "r"(a[3]), "r"(b0), "r"(b1));
}
__device__ __forceinline__ float ex2(float x) {
    float r;
    asm("ex2.approx.f32 %0, %1;" : "=f"(r) : "f"(x));
    return r;
}
__device__ __forceinline__ uint32_t pack_bf2(float a, float b) {
    uint32_t r;
    asm("cvt.rn.bf16x2.f32 %0, %1, %2;" : "=r"(r) : "f"(b), "f"(a));
    return r;
}
__device__ __forceinline__ float bf_lo(uint32_t v) { return __uint_as_float(v << 16); }
__device__ __forceinline__ float bf_hi(uint32_t v) { return __uint_as_float(v & 0xFFFF0000u); }

// ---------------------------------------------------------------------------
// fp32 -> bf16 hi/lo splits for input matrices
// ---------------------------------------------------------------------------
__device__ __forceinline__ void split_one(const float4* __restrict__ src,
                                          __nv_bfloat162* __restrict__ hi,
                                          __nv_bfloat162* __restrict__ lo, int i)
{
    float4 v = src[i];
    __nv_bfloat16 h0 = __float2bfloat16(v.x), h1 = __float2bfloat16(v.y);
    __nv_bfloat16 h2 = __float2bfloat16(v.z), h3 = __float2bfloat16(v.w);
    float l0 = v.x - __bfloat162float(h0), l1 = v.y - __bfloat162float(h1);
    float l2 = v.z - __bfloat162float(h2), l3 = v.w - __bfloat162float(h3);
    hi[2 * i]     = __halves2bfloat162(h0, h1);
    hi[2 * i + 1] = __halves2bfloat162(h2, h3);
    lo[2 * i]     = __halves2bfloat162(__float2bfloat16(l0), __float2bfloat16(l1));
    lo[2 * i + 1] = __halves2bfloat162(__float2bfloat16(l2), __float2bfloat16(l3));
}

__global__ __launch_bounds__(256) void splitA_kernel(
    const float4* __restrict__ s0, const float4* __restrict__ s1,
    const float4* __restrict__ s2)
{
    const int y = blockIdx.y;
    const float4* src = y == 0 ? s0 : y == 1 ? s1 : s2;
    __nv_bfloat162* hi = (__nv_bfloat162*)(y == 0 ? g_xh : y == 1 ? g_wqh : g_wkh);
    __nv_bfloat162* lo = (__nv_bfloat162*)(y == 0 ? g_xl : y == 1 ? g_wql : g_wkl);
    split_one(src, hi, lo, blockIdx.x * 256 + threadIdx.x);
}

__global__ __launch_bounds__(256) void splitB_kernel(
    const float4* __restrict__ s0, const float4* __restrict__ s1)
{
    const int y = blockIdx.y;
    const float4* src = y == 0 ? s0 : s1;
    __nv_bfloat162* hi = (__nv_bfloat162*)(y == 0 ? g_wvh : g_woh);
    __nv_bfloat162* lo = (__nv_bfloat162*)(y == 0 ? g_wvl : g_wol);
    split_one(src, hi, lo, blockIdx.x * 256 + threadIdx.x);
}

// context bias fp32 -> bf16
__global__ __launch_bounds__(256) void bias_bf16_kernel(const float2* __restrict__ cb)
{
    int i = blockIdx.x * 256 + threadIdx.x;
    float2 v = cb[i];
    ((__nv_bfloat162*)g_cb)[i] = __halves2bfloat162(__float2bfloat16(v.x),
                                                    __float2bfloat16(v.y));
}

// ---------------------------------------------------------------------------
// RoPE + hi/lo split for Q,K
// ---------------------------------------------------------------------------
__global__ __launch_bounds__(256) void rope_split_kernel()
{
    int idx = blockIdx.x * 256 + threadIdx.x;
    int i = idx & 31;
    int t = (idx >> 5) & (T_DIM - 1);
    int h = idx >> 16;

    float f = exp2f(-(float)i * 0.41524101186092030f);   // 10000^(-i/32)
    float ang = (float)t * f;
    float c = cosf(ang), s = sinf(ang);

    size_t base = ((size_t)h * T_DIM + t) * HD_DIM + i;
    float q1 = g_Q[base], q2 = g_Q[base + 32];
    float qa = q1 * c - q2 * s;
    float qb = q2 * c + q1 * s;
    float k1 = g_K[base], k2 = g_K[base + 32];
    float ka = k1 * c - k2 * s;
    float kb = k2 * c + k1 * s;

    __nv_bfloat16 hqa = __float2bfloat16(qa), hqb = __float2bfloat16(qb);
    __nv_bfloat16 hka = __float2bfloat16(ka), hkb = __float2bfloat16(kb);
    g_Qh[base]      = hqa; g_Ql[base]      = __float2bfloat16(qa - __bfloat162float(hqa));
    g_Qh[base + 32] = hqb; g_Ql[base + 32] = __float2bfloat16(qb - __bfloat162float(hqb));
    g_Kh[base]      = hka; g_Kl[base]      = __float2bfloat16(ka - __bfloat162float(hka));
    g_Kh[base + 32] = hkb; g_Kl[base + 32] = __float2bfloat16(kb - __bfloat162float(hkb));
}

// ---------------------------------------------------------------------------
// GEMM core (CTA 128x128, BK=32, 2-stage cp.async double buffer,
// 2 CTAs/SM, bf16 hi/lo 3-pass, PASS-MAJOR mma order for ILP)
// ---------------------------------------------------------------------------
#define ROWB      80
#define ARR_BYTES (128 * ROWB)
#define STG_BYTES (4 * ARR_BYTES)       // 40960
#define GEMM_SMEM (2 * STG_BYTES)       // 80 KB -> 2 CTAs/SM

__device__ __forceinline__ void g_load_stage(
    uint32_t st, const __nv_bfloat16* __restrict__ Ah, const __nv_bfloat16* __restrict__ Al,
    const __nv_bfloat16* __restrict__ Bh, const __nv_bfloat16* __restrict__ Bl,
    int t0, int o0, int k0, int tid)
{
    const int r = tid >> 2;
    const int c = (tid & 3);
    const int e = c * 8;
#pragma unroll
    for (int half = 0; half < 2; half++) {
        int row = r + half * 64;
        uint32_t so = row * ROWB + c * 16;
        size_t ga = (size_t)(t0 + row) * D_DIM + k0 + e;
        size_t gb = (size_t)(o0 + row) * D_DIM + k0 + e;
        cp16(st + so,                 Ah + ga);
        cp16(st + ARR_BYTES + so,     Al + ga);
        cp16(st + 2 * ARR_BYTES + so, Bh + gb);
        cp16(st + 3 * ARR_BYTES + so, Bl + gb);
    }
    cp_commit();
}

__device__ __forceinline__ void gemm_mainloop(
    uint32_t sb, const __nv_bfloat16* Ah, const __nv_bfloat16* Al,
    const __nv_bfloat16* Bh, const __nv_bfloat16* Bl,
    int t0, int o0, int tid, float acc[4][4][4])
{
    const int w    = tid >> 5;
    const int lane = tid & 31;
    const int wm0 = (w >> 2) * 64;
    const int wn0 = (w & 3) * 32;

#pragma unroll
    for (int i = 0; i < 4; i++)
#pragma unroll
        for (int j = 0; j < 4; j++)
#pragma unroll
            for (int q = 0; q < 4; q++) acc[i][j][q] = 0.f;

    g_load_stage(sb, Ah, Al, Bh, Bl, t0, o0, 0, tid);

    const int lm = lane & 15;
    const uint32_t kb = (uint32_t)(lane >> 4) * 16;

    for (int it = 0; it < 64; it++) {
        __syncthreads();                 // compute(it-1) done by all warps
        if (it + 1 < 64) {
            g_load_stage(sb + (uint32_t)((it + 1) & 1) * STG_BYTES,
                         Ah, Al, Bh, Bl, t0, o0, (it + 1) * 32, tid);
            cp_wait1();                  // stage it complete, it+1 in flight
        } else {
            cp_wait0();                  // last stage complete
        }
        __syncthreads();                 // stage it visible to all warps

        const uint32_t st = sb + (uint32_t)(it & 1) * STG_BYTES;
        const uint32_t aA = st + (uint32_t)(wm0 + lm) * ROWB + kb;
        const uint32_t aB = st + 2u * ARR_BYTES + (uint32_t)(wn0 + lm) * ROWB + kb;

#pragma unroll
        for (int ks = 0; ks < 2; ks++) {
            const uint32_t ko = (uint32_t)ks * 32;
            uint32_t ah[4][4], al[4][4], bh[2][4], bl[2][4];
#pragma unroll
            for (int i = 0; i < 4; i++) {
                ldm_x4(ah[i], aA + (uint32_t)(i * 16) * ROWB + ko);
                ldm_x4(al[i], aA + ARR_BYTES + (uint32_t)(i * 16) * ROWB + ko);
            }
#pragma unroll
            for (int j = 0; j < 2; j++) {
                ldm_x4(bh[j], aB + (uint32_t)(j * 16) * ROWB + ko);
                ldm_x4(bl[j], aB + ARR_BYTES + (uint32_t)(j * 16) * ROWB + ko);
            }
            // PASS-MAJOR: each accumulator touched once per pass; adjacent
            // HMMAs are independent (reuse distance 16, covers HMMA latency).
#pragma unroll
            for (int i = 0; i < 4; i++)
#pragma unroll
                for (int nj = 0; nj < 4; nj++) {
                    const int g = nj >> 1, o = nj & 1;
                    mma16816(acc[i][nj], ah[i], bh[g][o], bh[g][2 + o]);
                }
#pragma unroll
            for (int i = 0; i < 4; i++)
#pragma unroll
                for (int nj = 0; nj < 4; nj++) {
                    const int g = nj >> 1, o = nj & 1;
                    mma16816(acc[i][nj], ah[i], bl[g][o], bl[g][2 + o]);
                }
#pragma unroll
            for (int i = 0; i < 4; i++)
#pragma unroll
                for (int nj = 0; nj < 4; nj++) {
                    const int g = nj >> 1, o = nj & 1;
                    mma16816(acc[i][nj], al[i], bh[g][o], bh[g][2 + o]);
                }
        }
    }
    __syncthreads();
}

// QKV projections, one launch. z=0: Q, z=1: K (fp32 head layout),
// z=2: V (bf16 hi/lo head layout).
__global__ __launch_bounds__(256, 2) void gemm_qkv_kernel()
{
    extern __shared__ char smem[];
    const uint32_t sb = s2u(smem);
    const int tid = threadIdx.x;
    const int t0 = blockIdx.x * 128;
    const int o0 = blockIdx.y * 128;
    const int z  = blockIdx.z;

    const __nv_bfloat16* Bh = z == 0 ? g_wqh : z == 1 ? g_wkh : g_wvh;
    const __nv_bfloat16* Bl = z == 0 ? g_wql : z == 1 ? g_wkl : g_wvl;

    float acc[4][4][4];
    gemm_mainloop(sb, g_xh, g_xl, Bh, Bl, t0, o0, tid, acc);

    const int lane = tid & 31;
    const int w = tid >> 5;
    const int wm0 = (w >> 2) * 64, wn0 = (w & 3) * 32;
    const int tr = lane >> 2, tc = (lane & 3) * 2;
#pragma unroll
    for (int i = 0; i < 4; i++) {
#pragma unroll
        for (int nj = 0; nj < 4; nj++) {
            const int m0 = t0 + wm0 + i * 16 + tr;
            const int n  = o0 + wn0 + nj * 8 + tc;
            float2 v0 = make_float2(acc[i][nj][0], acc[i][nj][1]);
            float2 v1 = make_float2(acc[i][nj][2], acc[i][nj][3]);
            size_t base = ((size_t)(n >> 6) * T_DIM) * HD_DIM + (n & 63);
            if (z < 2) {
                float* C = z == 0 ? g_Q : g_K;
                *(float2*)&C[base + (size_t)m0 * HD_DIM]       = v0;
                *(float2*)&C[base + (size_t)(m0 + 8) * HD_DIM] = v1;
            } else {
                uint32_t h0 = pack_bf2(v0.x, v0.y);
                uint32_t h1 = pack_bf2(v1.x, v1.y);
                uint32_t l0 = pack_bf2(v0.x - bf_lo(h0), v0.y - bf_hi(h0));
                uint32_t l1 = pack_bf2(v1.x - bf_lo(h1), v1.y - bf_hi(h1));
                *(uint32_t*)&g_Vh[base + (size_t)m0 * HD_DIM]       = h0;
                *(uint32_t*)&g_Vh[base + (size_t)(m0 + 8) * HD_DIM] = h1;
                *(uint32_t*)&g_Vl[base + (size_t)m0 * HD_DIM]       = l0;
                *(uint32_t*)&g_Vl[base + (size_t)(m0 + 8) * HD_DIM] = l1;
            }
        }
    }
}

// Output projection: out = O * Wo^T, O given as hi/lo bf16 [T][D]
__global__ __launch_bounds__(256, 2) void gemm_out_kernel(float* __restrict__ C)
{
    extern __shared__ char smem[];
    const uint32_t sb = s2u(smem);
    const int tid = threadIdx.x;
    const int t0 = blockIdx.x * 128;
    const int o0 = blockIdx.y * 128;

    float acc[4][4][4];
    gemm_mainloop(sb, g_oh, g_ol, g_woh, g_wol, t0, o0, tid, acc);

    const int lane = tid & 31;
    const int w = tid >> 5;
    const int wm0 = (w >> 2) * 64, wn0 = (w & 3) * 32;
    const int tr = lane >> 2, tc = (lane & 3) * 2;
#pragma unroll
    for (int i = 0; i < 4; i++) {
#pragma unroll
        for (int nj = 0; nj < 4; nj++) {
            const int m0 = t0 + wm0 + i * 16 + tr;
            const int n  = o0 + wn0 + nj * 8 + tc;
            *(float2*)&C[(size_t)m0 * D_DIM + n] =
                make_float2(acc[i][nj][0], acc[i][nj][1]);
            *(float2*)&C[(size_t)(m0 + 8) * D_DIM + n] =
                make_float2(acc[i][nj][2], acc[i][nj][3]);
        }
    }
}

// ---------------------------------------------------------------------------
// Tensor-core flash attention (unchanged, passing)
// ---------------------------------------------------------------------------
#define AROWB   144
#define ATILE_Q (128 * AROWB)           // 18432 (Q hi or lo)
#define KTILE   (64 * AROWB)            // 9216 (one 64-row array)
#define ASTG    (4 * KTILE)             // 36864 (Kh,Kl,Vh,Vl per stage)
#define ATT_SMEM (2 * ATILE_Q + 2 * ASTG)   // 110592 B
#define LOG2E 1.4426950408889634f

__device__ __forceinline__ void a_load_stage64(
    uint32_t st, const __nv_bfloat16* __restrict__ Kh, const __nv_bfloat16* __restrict__ Kl,
    const __nv_bfloat16* __restrict__ Vh, const __nv_bfloat16* __restrict__ Vl,
    int k0, int tid)
{
#pragma unroll
    for (int i = 0; i < 2; i++) {
        int q = tid + i * 256;          // 0..511
        int row = q >> 3, cc = q & 7;
        uint32_t so = row * AROWB + cc * 16;
        size_t g = (size_t)(k0 + row) * HD_DIM + cc * 8;
        cp16(st + so,             Kh + g);
        cp16(st + KTILE + so,     Kl + g);
        cp16(st + 2 * KTILE + so, Vh + g);
        cp16(st + 3 * KTILE + so, Vl + g);
    }
}

__global__ __launch_bounds__(256, 2) void attn_tc_kernel(
    const float* __restrict__ modw, const float* __restrict__ temps)
{
    extern __shared__ char smem[];
    const uint32_t sb = s2u(smem);
    const uint32_t sQh = sb, sQl = sb + ATILE_Q;
    const uint32_t sStage = sb + 2 * ATILE_Q;

    const int tid  = threadIdx.x;
    const int w    = tid >> 5;
    const int lane = tid & 31;
    const int qb = gridDim.x - 1 - blockIdx.x;   // heavy tiles first
    const int h  = blockIdx.y;
    const int q0 = qb * 128;

    const float wgt = modw[c_h2m[h]];
    const float A1  = 0.125f * temps[h] * wgt * LOG2E;
    const float B1  = wgt * LOG2E;

    const __nv_bfloat16* Qhg = g_Qh + ((size_t)h * T_DIM + q0) * HD_DIM;
    const __nv_bfloat16* Qlg = g_Ql + ((size_t)h * T_DIM + q0) * HD_DIM;
    const __nv_bfloat16* Khg = g_Kh + (size_t)h * T_DIM * HD_DIM;
    const __nv_bfloat16* Klg = g_Kl + (size_t)h * T_DIM * HD_DIM;
    const __nv_bfloat16* Vhg = g_Vh + (size_t)h * T_DIM * HD_DIM;
    const __nv_bfloat16* Vlg = g_Vl + (size_t)h * T_DIM * HD_DIM;

#pragma unroll
    for (int i = 0; i < 4; i++) {
        int q = tid + i * 256;
        int row = q >> 3, cc = q & 7;
        uint32_t so = row * AROWB + cc * 16;
        size_t g = (size_t)row * HD_DIM + cc * 8;
        cp16(sQh + so, Qhg + g);
        cp16(sQl + so, Qlg + g);
    }
    a_load_stage64(sStage, Khg, Klg, Vhg, Vlg, 0, tid);
    cp_commit();
    a_load_stage64(sStage + ASTG, Khg, Klg, Vhg, Vlg, 64, tid);
    cp_commit();

    const int wq  = w * 16;
    const int lm  = lane & 15;
    const uint32_t kboff = (uint32_t)(lane >> 4) * 16;
    const int r   = lane >> 2;
    const int c2  = (lane & 3) * 2;
    const int qr0 = q0 + wq + r;
    const int qr1 = qr0 + 8;

    float m0 = -1e30f, m1 = -1e30f, l0 = 0.f, l1 = 0.f;
    float o[8][4];
#pragma unroll
    for (int j = 0; j < 8; j++)
#pragma unroll
        for (int q = 0; q < 4; q++) o[j][q] = 0.f;

    const uint32_t aQh = sQh + (uint32_t)(wq + lm) * AROWB + kboff;
    const uint32_t aQl = sQl + (uint32_t)(wq + lm) * AROWB + kboff;

    const int nkb = 2 * qb + 2;        // 64-row K blocks covering [0, q0+128)

    for (int kb = 0; kb < nkb; kb++) {
        cp_wait1();
        __syncthreads();
        const uint32_t st = sStage + (uint32_t)(kb & 1) * ASTG;
        const bool diag = (kb >= nkb - 2);
        const int k0 = kb * 64;

        float s[8][4];
#pragma unroll
        for (int j = 0; j < 8; j++)
#pragma unroll
            for (int q = 0; q < 4; q++) s[j][q] = 0.f;

#pragma unroll
        for (int ks = 0; ks < 4; ks++) {
            const uint32_t ko = (uint32_t)ks * 32;
            uint32_t ah[4], al[4];
            ldm_x4(ah, aQh + ko);
            ldm_x4(al, aQl + ko);
#pragma unroll
            for (int ng = 0; ng < 4; ng++) {
                uint32_t bh[4], bl[4];
                const uint32_t aK = st + (uint32_t)(ng * 16 + lm) * AROWB + kboff + ko;
                ldm_x4(bh, aK);
                ldm_x4(bl, aK + KTILE);
                mma16816(s[2 * ng],     ah, bh[0], bh[2]);
                mma16816(s[2 * ng + 1], ah, bh[1], bh[3]);
                mma16816(s[2 * ng],     ah, bl[0], bl[2]);
                mma16816(s[2 * ng + 1], ah, bl[1], bl[3]);
                mma16816(s[2 * ng],     al, bh[0], bh[2]);
                mma16816(s[2 * ng + 1], al, bh[1], bh[3]);
            }
        }

        const __nv_bfloat16* br0 = g_cb + (size_t)qr0 * T_DIM + k0;
        const __nv_bfloat16* br1 = g_cb + (size_t)qr1 * T_DIM + k0;
        float vmax0 = -1e30f, vmax1 = -1e30f;
#pragma unroll
        for (int j = 0; j < 8; j++) {
            const int kc = j * 8 + c2;
            float2 b0 = __bfloat1622float2(*(const __nv_bfloat162*)(br0 + kc));
            float2 b1 = __bfloat1622float2(*(const __nv_bfloat162*)(br1 + kc));
            s[j][0] = s[j][0] * A1 + b0.x * B1;
            s[j][1] = s[j][1] * A1 + b0.y * B1;
            s[j][2] = s[j][2] * A1 + b1.x * B1;
            s[j][3] = s[j][3] * A1 + b1.y * B1;
            if (diag) {
                const int ka = k0 + kc;
                if (ka > qr0)     s[j][0] = -1e30f;
                if (ka + 1 > qr0) s[j][1] = -1e30f;
                if (ka > qr1)     s[j][2] = -1e30f;
                if (ka + 1 > qr1) s[j][3] = -1e30f;
            }
            vmax0 = fmaxf(vmax0, fmaxf(s[j][0], s[j][1]));
            vmax1 = fmaxf(vmax1, fmaxf(s[j][2], s[j][3]));
        }
        vmax0 = fmaxf(vmax0, __shfl_xor_sync(0xffffffffu, vmax0, 1));
        vmax0 = fmaxf(vmax0, __shfl_xor_sync(0xffffffffu, vmax0, 2));
        vmax1 = fmaxf(vmax1, __shfl_xor_sync(0xffffffffu, vmax1, 1));
        vmax1 = fmaxf(vmax1, __shfl_xor_sync(0xffffffffu, vmax1, 2));

        const float mn0 = fmaxf(m0, vmax0);
        const float mn1 = fmaxf(m1, vmax1);
        const float al0 = ex2(m0 - mn0);
        const float al1 = ex2(m1 - mn1);
        m0 = mn0; m1 = mn1;

        float rs0 = 0.f, rs1 = 0.f;
#pragma unroll
        for (int j = 0; j < 8; j++) {
            s[j][0] = ex2(s[j][0] - mn0);
            s[j][1] = ex2(s[j][1] - mn0);
            s[j][2] = ex2(s[j][2] - mn1);
            s[j][3] = ex2(s[j][3] - mn1);
            rs0 += s[j][0] + s[j][1];
            rs1 += s[j][2] + s[j][3];
        }
        rs0 += __shfl_xor_sync(0xffffffffu, rs0, 1);
        rs0 += __shfl_xor_sync(0xffffffffu, rs0, 2);
        rs1 += __shfl_xor_sync(0xffffffffu, rs1, 1);
        rs1 += __shfl_xor_sync(0xffffffffu, rs1, 2);
        l0 = l0 * al0 + rs0;
        l1 = l1 * al1 + rs1;

#pragma unroll
        for (int j = 0; j < 8; j++) {
            o[j][0] *= al0; o[j][1] *= al0;
            o[j][2] *= al1; o[j][3] *= al1;
        }

#pragma unroll
        for (int ks = 0; ks < 4; ks++) {
            uint32_t ph[4], pl[4];
#pragma unroll
            for (int u = 0; u < 2; u++) {
                const int j = 2 * ks + u;
                uint32_t d0 = pack_bf2(s[j][0], s[j][1]);
                uint32_t d1 = pack_bf2(s[j][2], s[j][3]);
                ph[u]     = d0;  ph[2 + u] = d1;
                pl[u]     = pack_bf2(s[j][0] - bf_lo(d0), s[j][1] - bf_hi(d0));
                pl[2 + u] = pack_bf2(s[j][2] - bf_lo(d1), s[j][3] - bf_hi(d1));
            }
            uint32_t pa_h[4] = { ph[0], ph[2], ph[1], ph[3] };
            uint32_t pa_l[4] = { pl[0], pl[2], pl[1], pl[3] };
#pragma unroll
            for (int nv = 0; nv < 2; nv++) {
#pragma unroll
                for (int half = 0; half < 2; half++) {
                    const int n0 = nv * 32 + half * 16;
                    const uint32_t aV = st + 2 * KTILE
                        + (uint32_t)(ks * 16 + lm) * AROWB
                        + (uint32_t)(n0 + ((lane >> 4) * 8)) * 2;
                    uint32_t vh[4], vl[4];
                    ldm_x4_t(vh, aV);
                    ldm_x4_t(vl, aV + KTILE);
                    const int jt = nv * 4 + half * 2;
                    mma16816(o[jt],     pa_h, vh[0], vh[1]);
                    mma16816(o[jt + 1], pa_h, vh[2], vh[3]);
                    mma16816(o[jt],     pa_h, vl[0], vl[1]);
                    mma16816(o[jt + 1], pa_h, vl[2], vl[3]);
                    mma16816(o[jt],     pa_l, vh[0], vh[1]);
                    mma16816(o[jt + 1], pa_l, vh[2], vh[3]);
                }
            }
        }

        __syncthreads();
        if (kb + 2 < nkb)
            a_load_stage64(sStage + (uint32_t)(kb & 1) * ASTG,
                           Khg, Klg, Vhg, Vlg, (kb + 2) * 64, tid);
        cp_commit();
    }

    const float inv0 = 1.f / l0, inv1 = 1.f / l1;
#pragma unroll
    for (int j = 0; j < 8; j++) {
        const int d = j * 8 + c2;
        float a0 = o[j][0] * inv0, a1 = o[j][1] * inv0;
        float b0 = o[j][2] * inv1, b1 = o[j][3] * inv1;
        uint32_t h0 = pack_bf2(a0, a1);
        uint32_t h1 = pack_bf2(b0, b1);
        uint32_t lo0 = pack_bf2(a0 - bf_lo(h0), a1 - bf_hi(h0));
        uint32_t lo1 = pack_bf2(b0 - bf_lo(h1), b1 - bf_hi(h1));
        size_t i0 = (size_t)qr0 * D_DIM + h * HD_DIM + d;
        size_t i1 = (size_t)qr1 * D_DIM + h * HD_DIM + d;
        *(uint32_t*)&g_oh[i0] = h0;  *(uint32_t*)&g_ol[i0] = lo0;
        *(uint32_t*)&g_oh[i1] = h1;  *(uint32_t*)&g_ol[i1] = lo1;
    }
}

// ---------------------------------------------------------------------------
extern "C" void kernel_launch(void* const* d_in, const int* in_sizes, int n_in,
                              void* d_out, int out_size)
{
    const float* x  = (const float*)d_in[0];
    const float* cb = (const float*)d_in[2];
    const float* mw = (const float*)d_in[3];
    const float* Wq = (const float*)d_in[4];
    const float* Wk = (const float*)d_in[5];
    const float* Wv = (const float*)d_in[6];
    const float* Wo = (const float*)d_in[7];
    const float* ts = (const float*)d_in[8];
    float* out = (float*)d_out;

    cudaFuncSetAttribute(gemm_qkv_kernel,
                         cudaFuncAttributeMaxDynamicSharedMemorySize, GEMM_SMEM);
    cudaFuncSetAttribute(gemm_out_kernel,
                         cudaFuncAttributeMaxDynamicSharedMemorySize, GEMM_SMEM);
    cudaFuncSetAttribute(attn_tc_kernel,
                         cudaFuncAttributeMaxDynamicSharedMemorySize, ATT_SMEM);

    splitA_kernel<<<dim3(4096, 3), 256>>>((const float4*)x, (const float4*)Wq,
                                          (const float4*)Wk);
    splitB_kernel<<<dim3(4096, 2), 256>>>((const float4*)Wv, (const float4*)Wo);
    bias_bf16_kernel<<<8192, 256>>>((const float2*)cb);

    gemm_qkv_kernel<<<dim3(16, 16, 3), 256, GEMM_SMEM>>>();

    rope_split_kernel<<<(H_NUM * T_DIM * 32) / 256, 256>>>();

    attn_tc_kernel<<<dim3(T_DIM / 128, H_NUM), 256, ATT_SMEM>>>(mw, ts);

    gemm_out_kernel<<<dim3(16, 16), 256, GEMM_SMEM>>>(out);
}

// round 15
// speedup vs baseline: 1.5089x; 1.4200x over previous
#include <cuda_runtime.h>
#include <cuda_bf16.h>
#include <math.h>
#include <stdint.h>

#define T_DIM 2048
#define D_DIM 2048
#define H_NUM 32
#define HD_DIM 64

// ---------------------------------------------------------------------------
// Scratch (__device__ globals; allocation-free rule)
// ---------------------------------------------------------------------------
__device__ float g_Q[H_NUM * T_DIM * HD_DIM];   // [H][T][64] fp32 (pre-RoPE)
__device__ float g_K[H_NUM * T_DIM * HD_DIM];
__device__ float g_O32[T_DIM * D_DIM];          // attn out, tf32-rounded fp32

// tf32-rounded (RNA) fp32 copies of inputs
__device__ float g_x32[D_DIM * D_DIM];
__device__ float g_wq32[D_DIM * D_DIM], g_wk32[D_DIM * D_DIM];
__device__ float g_wv32[D_DIM * D_DIM], g_wo32[D_DIM * D_DIM];

// RoPE'd Q/K and V, bf16 hi/lo, [H][T][64] (attention path)
__device__ __nv_bfloat16 g_Qh[H_NUM * T_DIM * HD_DIM], g_Ql[H_NUM * T_DIM * HD_DIM];
__device__ __nv_bfloat16 g_Kh[H_NUM * T_DIM * HD_DIM], g_Kl[H_NUM * T_DIM * HD_DIM];
__device__ __nv_bfloat16 g_Vh[H_NUM * T_DIM * HD_DIM], g_Vl[H_NUM * T_DIM * HD_DIM];
__device__ __nv_bfloat16 g_cb[T_DIM * T_DIM];   // context bias, bf16

// head -> module index, HEAD_COUNTS = {8,6,4,4,6,4}
__constant__ int c_h2m[H_NUM] = {0,0,0,0,0,0,0,0,
                                 1,1,1,1,1,1,
                                 2,2,2,2,
                                 3,3,3,3,
                                 4,4,4,4,4,4,
                                 5,5,5,5};

// ---------------------------------------------------------------------------
// PTX helpers
// ---------------------------------------------------------------------------
__device__ __forceinline__ uint32_t s2u(const void* p) {
    uint32_t a;
    asm("{ .reg .u64 t; cvta.to.shared.u64 t, %1; cvt.u32.u64 %0, t; }"
        : "=r"(a) : "l"(p));
    return a;
}
__device__ __forceinline__ void cp16(uint32_t d, const void* s) {
    asm volatile("cp.async.cg.shared.global [%0], [%1], 16;" :: "r"(d), "l"(s));
}
__device__ __forceinline__ void cp_commit() {
    asm volatile("cp.async.commit_group;" ::: "memory");
}
__device__ __forceinline__ void cp_wait0() {
    asm volatile("cp.async.wait_group 0;" ::: "memory");
}
__device__ __forceinline__ void cp_wait1() {
    asm volatile("cp.async.wait_group 1;" ::: "memory");
}
__device__ __forceinline__ void ldm_x4(uint32_t* r, uint32_t a) {
    asm volatile("ldmatrix.sync.aligned.m8n8.x4.shared.b16 {%0,%1,%2,%3}, [%4];"
                 : "=r"(r[0]), "=r"(r[1]), "=r"(r[2]), "=r"(r[3]) : "r"(a));
}
__device__ __forceinline__ void ldm_x4_t(uint32_t* r, uint32_t a) {
    asm volatile("ldmatrix.sync.aligned.m8n8.x4.trans.shared.b16 {%0,%1,%2,%3}, [%4];"
                 : "=r"(r[0]), "=r"(r[1]), "=r"(r[2]), "=r"(r[3]) : "r"(a));
}
// bf16 mma (attention)
__device__ __forceinline__ void mma16816(float* d, const uint32_t* a,
                                         uint32_t b0, uint32_t b1) {
    asm volatile("mma.sync.aligned.m16n8k16.row.col.f32.bf16.bf16.f32 "
        "{%0,%1,%2,%3},{%4,%5,%6,%7},{%8,%9},{%0,%1,%2,%3};"
        : "+f"(d[0]), "+f"(d[1]), "+f"(d[2]), "+f"(d[3])
        : "r"(a[0]), "r"(a[1]), "r"(a[2]), "r"(a[3]), "r"(b0), "r"(b1));
}
// tf32 mma (GEMMs): m16n8k8, A 4 regs, B 2 regs, fp32 accum
__device__ __forceinline__ void mma1688(float* d, const uint32_t* a,
                                        uint32_t b0, uint32_t b1) {
    asm volatile("mma.sync.aligned.m16n8k8.row.col.f32.tf32.tf32.f32 "
        "{%0,%1,%2,%3},{%4,%5,%6,%7},{%8,%9},{%0,%1,%2,%3};"
        : "+f"(d[0]), "+f"(d[1]), "+f"(d[2]), "+f"(d[3])
        : "r"(a[0]), "r"(a[1]), "r"(a[2]), "r"(a[3]), "r"(b0), "r"(b1));
}
__device__ __forceinline__ float ex2(float x) {
    float r;
    asm("ex2.approx.f32 %0, %1;" : "=f"(r) : "f"(x));
    return r;
}
__device__ __forceinline__ uint32_t pack_bf2(float a, float b) {
    uint32_t r;
    asm("cvt.rn.bf16x2.f32 %0, %1, %2;" : "=r"(r) : "f"(b), "f"(a));
    return r;
}
__device__ __forceinline__ float bf_lo(uint32_t v) { return __uint_as_float(v << 16); }
__device__ __forceinline__ float bf_hi(uint32_t v) { return __uint_as_float(v & 0xFFFF0000u); }
__device__ __forceinline__ uint32_t f2tf(float x) {   // RNA round to tf32
    uint32_t r;
    asm("cvt.rna.tf32.f32 %0, %1;" : "=r"(r) : "f"(x));
    return r;
}

// ---------------------------------------------------------------------------
// RNA tf32 pre-rounding of inputs (two launches keep gemm_qkv in 4th slot)
// ---------------------------------------------------------------------------
__device__ __forceinline__ void round_one(const float4* __restrict__ src,
                                          float4* __restrict__ dst, int i)
{
    float4 v = src[i];
    float4 o;
    o.x = __uint_as_float(f2tf(v.x));
    o.y = __uint_as_float(f2tf(v.y));
    o.z = __uint_as_float(f2tf(v.z));
    o.w = __uint_as_float(f2tf(v.w));
    dst[i] = o;
}

__global__ __launch_bounds__(256) void roundA_kernel(
    const float4* __restrict__ s0, const float4* __restrict__ s1,
    const float4* __restrict__ s2)
{
    const int y = blockIdx.y;
    const float4* src = y == 0 ? s0 : y == 1 ? s1 : s2;
    float4* dst = (float4*)(y == 0 ? g_x32 : y == 1 ? g_wq32 : g_wk32);
    round_one(src, dst, blockIdx.x * 256 + threadIdx.x);
}

__global__ __launch_bounds__(256) void roundB_kernel(
    const float4* __restrict__ s0, const float4* __restrict__ s1)
{
    const int y = blockIdx.y;
    const float4* src = y == 0 ? s0 : s1;
    float4* dst = (float4*)(y == 0 ? g_wv32 : g_wo32);
    round_one(src, dst, blockIdx.x * 256 + threadIdx.x);
}

// context bias fp32 -> bf16
__global__ __launch_bounds__(256) void bias_bf16_kernel(const float2* __restrict__ cb)
{
    int i = blockIdx.x * 256 + threadIdx.x;
    float2 v = cb[i];
    ((__nv_bfloat162*)g_cb)[i] = __halves2bfloat162(__float2bfloat16(v.x),
                                                    __float2bfloat16(v.y));
}

// ---------------------------------------------------------------------------
// RoPE + hi/lo split for Q,K
// ---------------------------------------------------------------------------
__global__ __launch_bounds__(256) void rope_split_kernel()
{
    int idx = blockIdx.x * 256 + threadIdx.x;
    int i = idx & 31;
    int t = (idx >> 5) & (T_DIM - 1);
    int h = idx >> 16;

    float f = exp2f(-(float)i * 0.41524101186092030f);   // 10000^(-i/32)
    float ang = (float)t * f;
    float c = cosf(ang), s = sinf(ang);

    size_t base = ((size_t)h * T_DIM + t) * HD_DIM + i;
    float q1 = g_Q[base], q2 = g_Q[base + 32];
    float qa = q1 * c - q2 * s;
    float qb = q2 * c + q1 * s;
    float k1 = g_K[base], k2 = g_K[base + 32];
    float ka = k1 * c - k2 * s;
    float kb = k2 * c + k1 * s;

    __nv_bfloat16 hqa = __float2bfloat16(qa), hqb = __float2bfloat16(qb);
    __nv_bfloat16 hka = __float2bfloat16(ka), hkb = __float2bfloat16(kb);
    g_Qh[base]      = hqa; g_Ql[base]      = __float2bfloat16(qa - __bfloat162float(hqa));
    g_Qh[base + 32] = hqb; g_Ql[base + 32] = __float2bfloat16(qb - __bfloat162float(hqb));
    g_Kh[base]      = hka; g_Kl[base]      = __float2bfloat16(ka - __bfloat162float(hka));
    g_Kh[base + 32] = hkb; g_Kl[base + 32] = __float2bfloat16(kb - __bfloat162float(hkb));
}

// ---------------------------------------------------------------------------
// TF32 GEMM core: C = A * W^T.  CTA 128x128, BK=32 floats, 2-stage
// double buffer, 2 CTAs/SM, single pass m16n8k8.
// Smem rows: 32 floats = 128B, padded to 144B (conflict-free ldmatrix).
// ---------------------------------------------------------------------------
#define ROWB32    144
#define ARR32     (128 * ROWB32)        // 18432
#define STG32     (2 * ARR32)           // 36864 (A, B)
#define GEMM_SMEM (2 * STG32)           // 73728 -> 2 CTAs/SM

__device__ __forceinline__ void g_load32(
    uint32_t st, const float* __restrict__ A, const float* __restrict__ B,
    int t0, int o0, int k0, int tid)
{
#pragma unroll
    for (int i = 0; i < 4; i++) {
        int q = tid + i * 256;          // 0..1023
        int row = q >> 3, ch = q & 7;   // 128 rows x 8 chunks(16B)
        uint32_t so = row * ROWB32 + ch * 16;
        cp16(st + so,         A + (size_t)(t0 + row) * D_DIM + k0 + ch * 4);
        cp16(st + ARR32 + so, B + (size_t)(o0 + row) * D_DIM + k0 + ch * 4);
    }
    cp_commit();
}

__device__ __forceinline__ void gemm_mainloop32(
    uint32_t sb, const float* A, const float* B,
    int t0, int o0, int tid, float acc[4][4][4])
{
    const int w    = tid >> 5;
    const int lane = tid & 31;
    const int wm0 = (w >> 2) * 64;      // warp M offset
    const int wn0 = (w & 3) * 32;       // warp N offset

#pragma unroll
    for (int i = 0; i < 4; i++)
#pragma unroll
        for (int j = 0; j < 4; j++)
#pragma unroll
            for (int q = 0; q < 4; q++) acc[i][j][q] = 0.f;

    g_load32(sb, A, B, t0, o0, 0, tid);

    // A-fragment addressing (m16k8 tf32 via ldmatrix.x4):
    //   tiles = {r0-7,c0-3},{r8-15,c0-3},{r0-7,c4-7},{r8-15,c4-7}
    const int lm = lane & 15;                         // row within m16
    const uint32_t kboff = (uint32_t)(lane >> 4) * 16; // 16B col window
    // B-fragment addressing (k8 x n8 pair): tiles =
    //   {n0-7,k0-3},{n0-7,k4-7},{n8-15,k0-3},{n8-15,k4-7}
    const int brow = (lane & 7) + ((lane & 16) ? 8 : 0);
    const uint32_t bcol = (lane & 8) ? 16u : 0u;

    for (int it = 0; it < 64; it++) {
        __syncthreads();                 // compute(it-1) done by all warps
        if (it + 1 < 64) {
            g_load32(sb + (uint32_t)((it + 1) & 1) * STG32,
                     A, B, t0, o0, (it + 1) * 32, tid);
            cp_wait1();
        } else {
            cp_wait0();
        }
        __syncthreads();                 // stage it visible

        const uint32_t st = sb + (uint32_t)(it & 1) * STG32;
        const uint32_t aA = st + (uint32_t)(wm0 + lm) * ROWB32 + kboff;
        const uint32_t aB = st + ARR32 + bcol;

#pragma unroll
        for (int ks = 0; ks < 4; ks++) {
            const uint32_t ko = (uint32_t)ks * 32;    // k8 = 32 bytes
            uint32_t a[4][4], bb[2][4];
#pragma unroll
            for (int i = 0; i < 4; i++)
                ldm_x4(a[i], aA + (uint32_t)(i * 16) * ROWB32 + ko);
#pragma unroll
            for (int j = 0; j < 2; j++)
                ldm_x4(bb[j], aB + (uint32_t)(wn0 + j * 16 + brow) * ROWB32 + ko);
#pragma unroll
            for (int i = 0; i < 4; i++)
#pragma unroll
                for (int nj = 0; nj < 4; nj++) {
                    const int jg = nj >> 1, sel = (nj & 1) * 2;
                    mma1688(acc[i][nj], a[i], bb[jg][sel], bb[jg][sel + 1]);
                }
        }
    }
    __syncthreads();
}

// QKV projections, one launch. z=0: Q, z=1: K (fp32 head layout),
// z=2: V (bf16 hi/lo head layout).
__global__ __launch_bounds__(256, 2) void gemm_qkv_kernel()
{
    extern __shared__ char smem[];
    const uint32_t sb = s2u(smem);
    const int tid = threadIdx.x;
    const int t0 = blockIdx.x * 128;
    const int o0 = blockIdx.y * 128;
    const int z  = blockIdx.z;

    const float* B = z == 0 ? g_wq32 : z == 1 ? g_wk32 : g_wv32;

    float acc[4][4][4];
    gemm_mainloop32(sb, g_x32, B, t0, o0, tid, acc);

    const int lane = tid & 31;
    const int w = tid >> 5;
    const int wm0 = (w >> 2) * 64, wn0 = (w & 3) * 32;
    const int tr = lane >> 2, tc = (lane & 3) * 2;
#pragma unroll
    for (int i = 0; i < 4; i++) {
#pragma unroll
        for (int nj = 0; nj < 4; nj++) {
            const int m0 = t0 + wm0 + i * 16 + tr;
            const int n  = o0 + wn0 + nj * 8 + tc;
            float2 v0 = make_float2(acc[i][nj][0], acc[i][nj][1]);
            float2 v1 = make_float2(acc[i][nj][2], acc[i][nj][3]);
            size_t base = ((size_t)(n >> 6) * T_DIM) * HD_DIM + (n & 63);
            if (z < 2) {
                float* C = z == 0 ? g_Q : g_K;
                *(float2*)&C[base + (size_t)m0 * HD_DIM]       = v0;
                *(float2*)&C[base + (size_t)(m0 + 8) * HD_DIM] = v1;
            } else {
                uint32_t h0 = pack_bf2(v0.x, v0.y);
                uint32_t h1 = pack_bf2(v1.x, v1.y);
                uint32_t l0 = pack_bf2(v0.x - bf_lo(h0), v0.y - bf_hi(h0));
                uint32_t l1 = pack_bf2(v1.x - bf_lo(h1), v1.y - bf_hi(h1));
                *(uint32_t*)&g_Vh[base + (size_t)m0 * HD_DIM]       = h0;
                *(uint32_t*)&g_Vh[base + (size_t)(m0 + 8) * HD_DIM] = h1;
                *(uint32_t*)&g_Vl[base + (size_t)m0 * HD_DIM]       = l0;
                *(uint32_t*)&g_Vl[base + (size_t)(m0 + 8) * HD_DIM] = l1;
            }
        }
    }
}

// Output projection: out = O * Wo^T (both tf32-rounded fp32)
__global__ __launch_bounds__(256, 2) void gemm_out_kernel(float* __restrict__ C)
{
    extern __shared__ char smem[];
    const uint32_t sb = s2u(smem);
    const int tid = threadIdx.x;
    const int t0 = blockIdx.x * 128;
    const int o0 = blockIdx.y * 128;

    float acc[4][4][4];
    gemm_mainloop32(sb, g_O32, g_wo32, t0, o0, tid, acc);

    const int lane = tid & 31;
    const int w = tid >> 5;
    const int wm0 = (w >> 2) * 64, wn0 = (w & 3) * 32;
    const int tr = lane >> 2, tc = (lane & 3) * 2;
#pragma unroll
    for (int i = 0; i < 4; i++) {
#pragma unroll
        for (int nj = 0; nj < 4; nj++) {
            const int m0 = t0 + wm0 + i * 16 + tr;
            const int n  = o0 + wn0 + nj * 8 + tc;
            *(float2*)&C[(size_t)m0 * D_DIM + n] =
                make_float2(acc[i][nj][0], acc[i][nj][1]);
            *(float2*)&C[(size_t)(m0 + 8) * D_DIM + n] =
                make_float2(acc[i][nj][2], acc[i][nj][3]);
        }
    }
}

// ---------------------------------------------------------------------------
// Tensor-core flash attention, bf16 hi/lo (unchanged except epilogue:
// writes tf32-rounded fp32 O for the tf32 output GEMM).
// ---------------------------------------------------------------------------
#define AROWB   144
#define ATILE_Q (128 * AROWB)
#define KTILE   (64 * AROWB)
#define ASTG    (4 * KTILE)
#define ATT_SMEM (2 * ATILE_Q + 2 * ASTG)   // 110592 B
#define LOG2E 1.4426950408889634f

__device__ __forceinline__ void a_load_stage64(
    uint32_t st, const __nv_bfloat16* __restrict__ Kh, const __nv_bfloat16* __restrict__ Kl,
    const __nv_bfloat16* __restrict__ Vh, const __nv_bfloat16* __restrict__ Vl,
    int k0, int tid)
{
#pragma unroll
    for (int i = 0; i < 2; i++) {
        int q = tid + i * 256;
        int row = q >> 3, cc = q & 7;
        uint32_t so = row * AROWB + cc * 16;
        size_t g = (size_t)(k0 + row) * HD_DIM + cc * 8;
        cp16(st + so,             Kh + g);
        cp16(st + KTILE + so,     Kl + g);
        cp16(st + 2 * KTILE + so, Vh + g);
        cp16(st + 3 * KTILE + so, Vl + g);
    }
}

__global__ __launch_bounds__(256, 2) void attn_tc_kernel(
    const float* __restrict__ modw, const float* __restrict__ temps)
{
    extern __shared__ char smem[];
    const uint32_t sb = s2u(smem);
    const uint32_t sQh = sb, sQl = sb + ATILE_Q;
    const uint32_t sStage = sb + 2 * ATILE_Q;

    const int tid  = threadIdx.x;
    const int w    = tid >> 5;
    const int lane = tid & 31;
    const int qb = gridDim.x - 1 - blockIdx.x;
    const int h  = blockIdx.y;
    const int q0 = qb * 128;

    const float wgt = modw[c_h2m[h]];
    const float A1  = 0.125f * temps[h] * wgt * LOG2E;
    const float B1  = wgt * LOG2E;

    const __nv_bfloat16* Qhg = g_Qh + ((size_t)h * T_DIM + q0) * HD_DIM;
    const __nv_bfloat16* Qlg = g_Ql + ((size_t)h * T_DIM + q0) * HD_DIM;
    const __nv_bfloat16* Khg = g_Kh + (size_t)h * T_DIM * HD_DIM;
    const __nv_bfloat16* Klg = g_Kl + (size_t)h * T_DIM * HD_DIM;
    const __nv_bfloat16* Vhg = g_Vh + (size_t)h * T_DIM * HD_DIM;
    const __nv_bfloat16* Vlg = g_Vl + (size_t)h * T_DIM * HD_DIM;

#pragma unroll
    for (int i = 0; i < 4; i++) {
        int q = tid + i * 256;
        int row = q >> 3, cc = q & 7;
        uint32_t so = row * AROWB + cc * 16;
        size_t g = (size_t)row * HD_DIM + cc * 8;
        cp16(sQh + so, Qhg + g);
        cp16(sQl + so, Qlg + g);
    }
    a_load_stage64(sStage, Khg, Klg, Vhg, Vlg, 0, tid);
    cp_commit();
    a_load_stage64(sStage + ASTG, Khg, Klg, Vhg, Vlg, 64, tid);
    cp_commit();

    const int wq  = w * 16;
    const int lm  = lane & 15;
    const uint32_t kboff = (uint32_t)(lane >> 4) * 16;
    const int r   = lane >> 2;
    const int c2  = (lane & 3) * 2;
    const int qr0 = q0 + wq + r;
    const int qr1 = qr0 + 8;

    float m0 = -1e30f, m1 = -1e30f, l0 = 0.f, l1 = 0.f;
    float o[8][4];
#pragma unroll
    for (int j = 0; j < 8; j++)
#pragma unroll
        for (int q = 0; q < 4; q++) o[j][q] = 0.f;

    const uint32_t aQh = sQh + (uint32_t)(wq + lm) * AROWB + kboff;
    const uint32_t aQl = sQl + (uint32_t)(wq + lm) * AROWB + kboff;

    const int nkb = 2 * qb + 2;

    for (int kb = 0; kb < nkb; kb++) {
        cp_wait1();
        __syncthreads();
        const uint32_t st = sStage + (uint32_t)(kb & 1) * ASTG;
        const bool diag = (kb >= nkb - 2);
        const int k0 = kb * 64;

        float s[8][4];
#pragma unroll
        for (int j = 0; j < 8; j++)
#pragma unroll
            for (int q = 0; q < 4; q++) s[j][q] = 0.f;

#pragma unroll
        for (int ks = 0; ks < 4; ks++) {
            const uint32_t ko = (uint32_t)ks * 32;
            uint32_t ah[4], al[4];
            ldm_x4(ah, aQh + ko);
            ldm_x4(al, aQl + ko);
#pragma unroll
            for (int ng = 0; ng < 4; ng++) {
                uint32_t bh[4], bl[4];
                const uint32_t aK = st + (uint32_t)(ng * 16 + lm) * AROWB + kboff + ko;
                ldm_x4(bh, aK);
                ldm_x4(bl, aK + KTILE);
                mma16816(s[2 * ng],     ah, bh[0], bh[2]);
                mma16816(s[2 * ng + 1], ah, bh[1], bh[3]);
                mma16816(s[2 * ng],     ah, bl[0], bl[2]);
                mma16816(s[2 * ng + 1], ah, bl[1], bl[3]);
                mma16816(s[2 * ng],     al, bh[0], bh[2]);
                mma16816(s[2 * ng + 1], al, bh[1], bh[3]);
            }
        }

        const __nv_bfloat16* br0 = g_cb + (size_t)qr0 * T_DIM + k0;
        const __nv_bfloat16* br1 = g_cb + (size_t)qr1 * T_DIM + k0;
        float vmax0 = -1e30f, vmax1 = -1e30f;
#pragma unroll
        for (int j = 0; j < 8; j++) {
            const int kc = j * 8 + c2;
            float2 b0 = __bfloat1622float2(*(const __nv_bfloat162*)(br0 + kc));
            float2 b1 = __bfloat1622float2(*(const __nv_bfloat162*)(br1 + kc));
            s[j][0] = s[j][0] * A1 + b0.x * B1;
            s[j][1] = s[j][1] * A1 + b0.y * B1;
            s[j][2] = s[j][2] * A1 + b1.x * B1;
            s[j][3] = s[j][3] * A1 + b1.y * B1;
            if (diag) {
                const int ka = k0 + kc;
                if (ka > qr0)     s[j][0] = -1e30f;
                if (ka + 1 > qr0) s[j][1] = -1e30f;
                if (ka > qr1)     s[j][2] = -1e30f;
                if (ka + 1 > qr1) s[j][3] = -1e30f;
            }
            vmax0 = fmaxf(vmax0, fmaxf(s[j][0], s[j][1]));
            vmax1 = fmaxf(vmax1, fmaxf(s[j][2], s[j][3]));
        }
        vmax0 = fmaxf(vmax0, __shfl_xor_sync(0xffffffffu, vmax0, 1));
        vmax0 = fmaxf(vmax0, __shfl_xor_sync(0xffffffffu, vmax0, 2));
        vmax1 = fmaxf(vmax1, __shfl_xor_sync(0xffffffffu, vmax1, 1));
        vmax1 = fmaxf(vmax1, __shfl_xor_sync(0xffffffffu, vmax1, 2));

        const float mn0 = fmaxf(m0, vmax0);
        const float mn1 = fmaxf(m1, vmax1);
        const float al0 = ex2(m0 - mn0);
        const float al1 = ex2(m1 - mn1);
        m0 = mn0; m1 = mn1;

        float rs0 = 0.f, rs1 = 0.f;
#pragma unroll
        for (int j = 0; j < 8; j++) {
            s[j][0] = ex2(s[j][0] - mn0);
            s[j][1] = ex2(s[j][1] - mn0);
            s[j][2] = ex2(s[j][2] - mn1);
            s[j][3] = ex2(s[j][3] - mn1);
            rs0 += s[j][0] + s[j][1];
            rs1 += s[j][2] + s[j][3];
        }
        rs0 += __shfl_xor_sync(0xffffffffu, rs0, 1);
        rs0 += __shfl_xor_sync(0xffffffffu, rs0, 2);
        rs1 += __shfl_xor_sync(0xffffffffu, rs1, 1);
        rs1 += __shfl_xor_sync(0xffffffffu, rs1, 2);
        l0 = l0 * al0 + rs0;
        l1 = l1 * al1 + rs1;

#pragma unroll
        for (int j = 0; j < 8; j++) {
            o[j][0] *= al0; o[j][1] *= al0;
            o[j][2] *= al1; o[j][3] *= al1;
        }

#pragma unroll
        for (int ks = 0; ks < 4; ks++) {
            uint32_t ph[4], pl[4];
#pragma unroll
            for (int u = 0; u < 2; u++) {
                const int j = 2 * ks + u;
                uint32_t d0 = pack_bf2(s[j][0], s[j][1]);
                uint32_t d1 = pack_bf2(s[j][2], s[j][3]);
                ph[u]     = d0;  ph[2 + u] = d1;
                pl[u]     = pack_bf2(s[j][0] - bf_lo(d0), s[j][1] - bf_hi(d0));
                pl[2 + u] = pack_bf2(s[j][2] - bf_lo(d1), s[j][3] - bf_hi(d1));
            }
            uint32_t pa_h[4] = { ph[0], ph[2], ph[1], ph[3] };
            uint32_t pa_l[4] = { pl[0], pl[2], pl[1], pl[3] };
#pragma unroll
            for (int nv = 0; nv < 2; nv++) {
#pragma unroll
                for (int half = 0; half < 2; half++) {
                    const int n0 = nv * 32 + half * 16;
                    const uint32_t aV = st + 2 * KTILE
                        + (uint32_t)(ks * 16 + lm) * AROWB
                        + (uint32_t)(n0 + ((lane >> 4) * 8)) * 2;
                    uint32_t vh[4], vl[4];
                    ldm_x4_t(vh, aV);
                    ldm_x4_t(vl, aV + KTILE);
                    const int jt = nv * 4 + half * 2;
                    mma16816(o[jt],     pa_h, vh[0], vh[1]);
                    mma16816(o[jt + 1], pa_h, vh[2], vh[3]);
                    mma16816(o[jt],     pa_h, vl[0], vl[1]);
                    mma16816(o[jt + 1], pa_h, vl[2], vl[3]);
                    mma16816(o[jt],     pa_l, vh[0], vh[1]);
                    mma16816(o[jt + 1], pa_l, vh[2], vh[3]);
                }
            }
        }

        __syncthreads();
        if (kb + 2 < nkb)
            a_load_stage64(sStage + (uint32_t)(kb & 1) * ASTG,
                           Khg, Klg, Vhg, Vlg, (kb + 2) * 64, tid);
        cp_commit();
    }

    // epilogue: normalize, RNA-round to tf32, write fp32 [T][D]
    const float inv0 = 1.f / l0, inv1 = 1.f / l1;
#pragma unroll
    for (int j = 0; j < 8; j++) {
        const int d = j * 8 + c2;
        size_t i0 = (size_t)qr0 * D_DIM + h * HD_DIM + d;
        size_t i1 = (size_t)qr1 * D_DIM + h * HD_DIM + d;
        *(float2*)&g_O32[i0] = make_float2(
            __uint_as_float(f2tf(o[j][0] * inv0)),
            __uint_as_float(f2tf(o[j][1] * inv0)));
        *(float2*)&g_O32[i1] = make_float2(
            __uint_as_float(f2tf(o[j][2] * inv1)),
            __uint_as_float(f2tf(o[j][3] * inv1)));
    }
}

// ---------------------------------------------------------------------------
extern "C" void kernel_launch(void* const* d_in, const int* in_sizes, int n_in,
                              void* d_out, int out_size)
{
    const float* x  = (const float*)d_in[0];
    const float* cb = (const float*)d_in[2];
    const float* mw = (const float*)d_in[3];
    const float* Wq = (const float*)d_in[4];
    const float* Wk = (const float*)d_in[5];
    const float* Wv = (const float*)d_in[6];
    const float* Wo = (const float*)d_in[7];
    const float* ts = (const float*)d_in[8];
    float* out = (float*)d_out;

    cudaFuncSetAttribute(gemm_qkv_kernel,
                         cudaFuncAttributeMaxDynamicSharedMemorySize, GEMM_SMEM);
    cudaFuncSetAttribute(gemm_out_kernel,
                         cudaFuncAttributeMaxDynamicSharedMemorySize, GEMM_SMEM);
    cudaFuncSetAttribute(attn_tc_kernel,
                         cudaFuncAttributeMaxDynamicSharedMemorySize, ATT_SMEM);

    roundA_kernel<<<dim3(4096, 3), 256>>>((const float4*)x, (const float4*)Wq,
                                          (const float4*)Wk);
    roundB_kernel<<<dim3(4096, 2), 256>>>((const float4*)Wv, (const float4*)Wo);
    bias_bf16_kernel<<<8192, 256>>>((const float2*)cb);

    gemm_qkv_kernel<<<dim3(16, 16, 3), 256, GEMM_SMEM>>>();

    rope_split_kernel<<<(H_NUM * T_DIM * 32) / 256, 256>>>();

    attn_tc_kernel<<<dim3(T_DIM / 128, H_NUM), 256, ATT_SMEM>>>(mw, ts);

    gemm_out_kernel<<<dim3(16, 16), 256, GEMM_SMEM>>>(out);
}

// round 16
// speedup vs baseline: 1.5377x; 1.0191x over previous
#include <cuda_runtime.h>
#include <cuda_bf16.h>
#include <math.h>
#include <stdint.h>

#define T_DIM 2048
#define D_DIM 2048
#define H_NUM 32
#define HD_DIM 64

// ---------------------------------------------------------------------------
// Scratch (__device__ globals; allocation-free rule)
// ---------------------------------------------------------------------------
__device__ float g_Q[H_NUM * T_DIM * HD_DIM];   // [H][T][64] fp32 (pre-RoPE)
__device__ float g_K[H_NUM * T_DIM * HD_DIM];
__device__ float g_O32[T_DIM * D_DIM];          // attn out, tf32-rounded fp32

// tf32-rounded (RNA) fp32 copies of inputs
__device__ float g_x32[D_DIM * D_DIM];
__device__ float g_wq32[D_DIM * D_DIM], g_wk32[D_DIM * D_DIM];
__device__ float g_wv32[D_DIM * D_DIM], g_wo32[D_DIM * D_DIM];

// RoPE'd Q/K and V, bf16 hi/lo, [H][T][64] (attention path)
__device__ __nv_bfloat16 g_Qh[H_NUM * T_DIM * HD_DIM], g_Ql[H_NUM * T_DIM * HD_DIM];
__device__ __nv_bfloat16 g_Kh[H_NUM * T_DIM * HD_DIM], g_Kl[H_NUM * T_DIM * HD_DIM];
__device__ __nv_bfloat16 g_Vh[H_NUM * T_DIM * HD_DIM], g_Vl[H_NUM * T_DIM * HD_DIM];
__device__ __nv_bfloat16 g_cb[T_DIM * T_DIM];   // context bias, bf16

// head -> module index, HEAD_COUNTS = {8,6,4,4,6,4}
__constant__ int c_h2m[H_NUM] = {0,0,0,0,0,0,0,0,
                                 1,1,1,1,1,1,
                                 2,2,2,2,
                                 3,3,3,3,
                                 4,4,4,4,4,4,
                                 5,5,5,5};

// ---------------------------------------------------------------------------
// PTX helpers
// ---------------------------------------------------------------------------
__device__ __forceinline__ uint32_t s2u(const void* p) {
    uint32_t a;
    asm("{ .reg .u64 t; cvta.to.shared.u64 t, %1; cvt.u32.u64 %0, t; }"
        : "=r"(a) : "l"(p));
    return a;
}
__device__ __forceinline__ void cp16(uint32_t d, const void* s) {
    asm volatile("cp.async.cg.shared.global [%0], [%1], 16;" :: "r"(d), "l"(s));
}
__device__ __forceinline__ void cp_commit() {
    asm volatile("cp.async.commit_group;" ::: "memory");
}
__device__ __forceinline__ void cp_wait0() {
    asm volatile("cp.async.wait_group 0;" ::: "memory");
}
__device__ __forceinline__ void ldm_x4(uint32_t* r, uint32_t a) {
    asm volatile("ldmatrix.sync.aligned.m8n8.x4.shared.b16 {%0,%1,%2,%3}, [%4];"
                 : "=r"(r[0]), "=r"(r[1]), "=r"(r[2]), "=r"(r[3]) : "r"(a));
}
__device__ __forceinline__ void ldm_x4_t(uint32_t* r, uint32_t a) {
    asm volatile("ldmatrix.sync.aligned.m8n8.x4.trans.shared.b16 {%0,%1,%2,%3}, [%4];"
                 : "=r"(r[0]), "=r"(r[1]), "=r"(r[2]), "=r"(r[3]) : "r"(a));
}
// bf16 mma (attention)
__device__ __forceinline__ void mma16816(float* d, const uint32_t* a,
                                         uint32_t b0, uint32_t b1) {
    asm volatile("mma.sync.aligned.m16n8k16.row.col.f32.bf16.bf16.f32 "
        "{%0,%1,%2,%3},{%4,%5,%6,%7},{%8,%9},{%0,%1,%2,%3};"
        : "+f"(d[0]), "+f"(d[1]), "+f"(d[2]), "+f"(d[3])
        : "r"(a[0]), "r"(a[1]), "r"(a[2]), "r"(a[3]), "r"(b0), "r"(b1));
}
// tf32 mma (GEMMs): m16n8k8, A 4 regs, B 2 regs, fp32 accum
__device__ __forceinline__ void mma1688(float* d, const uint32_t* a,
                                        uint32_t b0, uint32_t b1) {
    asm volatile("mma.sync.aligned.m16n8k8.row.col.f32.tf32.tf32.f32 "
        "{%0,%1,%2,%3},{%4,%5,%6,%7},{%8,%9},{%0,%1,%2,%3};"
        : "+f"(d[0]), "+f"(d[1]), "+f"(d[2]), "+f"(d[3])
        : "r"(a[0]), "r"(a[1]), "r"(a[2]), "r"(a[3]), "r"(b0), "r"(b1));
}
__device__ __forceinline__ float ex2(float x) {
    float r;
    asm("ex2.approx.f32 %0, %1;" : "=f"(r) : "f"(x));
    return r;
}
__device__ __forceinline__ uint32_t pack_bf2(float a, float b) {
    uint32_t r;
    asm("cvt.rn.bf16x2.f32 %0, %1, %2;" : "=r"(r) : "f"(b), "f"(a));
    return r;
}
__device__ __forceinline__ float bf_lo(uint32_t v) { return __uint_as_float(v << 16); }
__device__ __forceinline__ float bf_hi(uint32_t v) { return __uint_as_float(v & 0xFFFF0000u); }
__device__ __forceinline__ uint32_t f2tf(float x) {   // RNA round to tf32
    uint32_t r;
    asm("cvt.rna.tf32.f32 %0, %1;" : "=r"(r) : "f"(x));
    return r;
}

// ---------------------------------------------------------------------------
// RNA tf32 pre-rounding of inputs (two launches keep gemm_qkv in 4th slot)
// ---------------------------------------------------------------------------
__device__ __forceinline__ void round_one(const float4* __restrict__ src,
                                          float4* __restrict__ dst, int i)
{
    float4 v = src[i];
    float4 o;
    o.x = __uint_as_float(f2tf(v.x));
    o.y = __uint_as_float(f2tf(v.y));
    o.z = __uint_as_float(f2tf(v.z));
    o.w = __uint_as_float(f2tf(v.w));
    dst[i] = o;
}

__global__ __launch_bounds__(256) void roundA_kernel(
    const float4* __restrict__ s0, const float4* __restrict__ s1,
    const float4* __restrict__ s2)
{
    const int y = blockIdx.y;
    const float4* src = y == 0 ? s0 : y == 1 ? s1 : s2;
    float4* dst = (float4*)(y == 0 ? g_x32 : y == 1 ? g_wq32 : g_wk32);
    round_one(src, dst, blockIdx.x * 256 + threadIdx.x);
}

__global__ __launch_bounds__(256) void roundB_kernel(
    const float4* __restrict__ s0, const float4* __restrict__ s1)
{
    const int y = blockIdx.y;
    const float4* src = y == 0 ? s0 : s1;
    float4* dst = (float4*)(y == 0 ? g_wv32 : g_wo32);
    round_one(src, dst, blockIdx.x * 256 + threadIdx.x);
}

// context bias fp32 -> bf16
__global__ __launch_bounds__(256) void bias_bf16_kernel(const float2* __restrict__ cb)
{
    int i = blockIdx.x * 256 + threadIdx.x;
    float2 v = cb[i];
    ((__nv_bfloat162*)g_cb)[i] = __halves2bfloat162(__float2bfloat16(v.x),
                                                    __float2bfloat16(v.y));
}

// ---------------------------------------------------------------------------
// RoPE + hi/lo split for Q,K
// ---------------------------------------------------------------------------
__global__ __launch_bounds__(256) void rope_split_kernel()
{
    int idx = blockIdx.x * 256 + threadIdx.x;
    int i = idx & 31;
    int t = (idx >> 5) & (T_DIM - 1);
    int h = idx >> 16;

    float f = exp2f(-(float)i * 0.41524101186092030f);   // 10000^(-i/32)
    float ang = (float)t * f;
    float c = cosf(ang), s = sinf(ang);

    size_t base = ((size_t)h * T_DIM + t) * HD_DIM + i;
    float q1 = g_Q[base], q2 = g_Q[base + 32];
    float qa = q1 * c - q2 * s;
    float qb = q2 * c + q1 * s;
    float k1 = g_K[base], k2 = g_K[base + 32];
    float ka = k1 * c - k2 * s;
    float kb = k2 * c + k1 * s;

    __nv_bfloat16 hqa = __float2bfloat16(qa), hqb = __float2bfloat16(qb);
    __nv_bfloat16 hka = __float2bfloat16(ka), hkb = __float2bfloat16(kb);
    g_Qh[base]      = hqa; g_Ql[base]      = __float2bfloat16(qa - __bfloat162float(hqa));
    g_Qh[base + 32] = hqb; g_Ql[base + 32] = __float2bfloat16(qb - __bfloat162float(hqb));
    g_Kh[base]      = hka; g_Kl[base]      = __float2bfloat16(ka - __bfloat162float(hka));
    g_Kh[base + 32] = hkb; g_Kl[base + 32] = __float2bfloat16(kb - __bfloat162float(hkb));
}

// ---------------------------------------------------------------------------
// TF32 GEMM core: C = A * W^T.  CTA 128x128, BK=32 floats, 2-stage
// double buffer, 2 CTAs/SM, single pass m16n8k8, ONE barrier per iter:
//   wait0 -> barrier -> issue(it+1) -> compute(it)
// Safety: barrier at iter it certifies every warp finished iter it-1
// (compute(it-1) + its wait), so issue(it+1) may overwrite buffer
// (it+1)&1 == (it-1)&1, and all stage-it copies are visible.
// ---------------------------------------------------------------------------
#define ROWB32    144
#define ARR32     (128 * ROWB32)        // 18432
#define STG32     (2 * ARR32)           // 36864 (A, B)
#define GEMM_SMEM (2 * STG32)           // 73728 -> 2 CTAs/SM

__device__ __forceinline__ void g_load32(
    uint32_t st, const float* __restrict__ A, const float* __restrict__ B,
    int t0, int o0, int k0, int tid)
{
#pragma unroll
    for (int i = 0; i < 4; i++) {
        int q = tid + i * 256;          // 0..1023
        int row = q >> 3, ch = q & 7;   // 128 rows x 8 chunks(16B)
        uint32_t so = row * ROWB32 + ch * 16;
        cp16(st + so,         A + (size_t)(t0 + row) * D_DIM + k0 + ch * 4);
        cp16(st + ARR32 + so, B + (size_t)(o0 + row) * D_DIM + k0 + ch * 4);
    }
    cp_commit();
}

__device__ __forceinline__ void gemm_mainloop32(
    uint32_t sb, const float* A, const float* B,
    int t0, int o0, int tid, float acc[4][4][4])
{
    const int w    = tid >> 5;
    const int lane = tid & 31;
    const int wm0 = (w >> 2) * 64;      // warp M offset
    const int wn0 = (w & 3) * 32;       // warp N offset

#pragma unroll
    for (int i = 0; i < 4; i++)
#pragma unroll
        for (int j = 0; j < 4; j++)
#pragma unroll
            for (int q = 0; q < 4; q++) acc[i][j][q] = 0.f;

    g_load32(sb, A, B, t0, o0, 0, tid);

    const int lm = lane & 15;
    const uint32_t kboff = (uint32_t)(lane >> 4) * 16;
    const int brow = (lane & 7) + ((lane & 16) ? 8 : 0);
    const uint32_t bcol = (lane & 8) ? 16u : 0u;

    for (int it = 0; it < 64; it++) {
        cp_wait0();                      // my stage-it copies done
        __syncthreads();                 // everyone's done + compute(it-1) done
        if (it + 1 < 64)
            g_load32(sb + (uint32_t)((it + 1) & 1) * STG32,
                     A, B, t0, o0, (it + 1) * 32, tid);

        const uint32_t st = sb + (uint32_t)(it & 1) * STG32;
        const uint32_t aA = st + (uint32_t)(wm0 + lm) * ROWB32 + kboff;
        const uint32_t aB = st + ARR32 + bcol;

#pragma unroll
        for (int ks = 0; ks < 4; ks++) {
            const uint32_t ko = (uint32_t)ks * 32;    // k8 = 32 bytes
            uint32_t a[4][4], bb[2][4];
#pragma unroll
            for (int i = 0; i < 4; i++)
                ldm_x4(a[i], aA + (uint32_t)(i * 16) * ROWB32 + ko);
#pragma unroll
            for (int j = 0; j < 2; j++)
                ldm_x4(bb[j], aB + (uint32_t)(wn0 + j * 16 + brow) * ROWB32 + ko);
#pragma unroll
            for (int i = 0; i < 4; i++)
#pragma unroll
                for (int nj = 0; nj < 4; nj++) {
                    const int jg = nj >> 1, sel = (nj & 1) * 2;
                    mma1688(acc[i][nj], a[i], bb[jg][sel], bb[jg][sel + 1]);
                }
        }
    }
    __syncthreads();
}

// QKV projections, one launch. z=0: Q, z=1: K (fp32 head layout),
// z=2: V (bf16 hi/lo head layout).
__global__ __launch_bounds__(256, 2) void gemm_qkv_kernel()
{
    extern __shared__ char smem[];
    const uint32_t sb = s2u(smem);
    const int tid = threadIdx.x;
    const int t0 = blockIdx.x * 128;
    const int o0 = blockIdx.y * 128;
    const int z  = blockIdx.z;

    const float* B = z == 0 ? g_wq32 : z == 1 ? g_wk32 : g_wv32;

    float acc[4][4][4];
    gemm_mainloop32(sb, g_x32, B, t0, o0, tid, acc);

    const int lane = tid & 31;
    const int w = tid >> 5;
    const int wm0 = (w >> 2) * 64, wn0 = (w & 3) * 32;
    const int tr = lane >> 2, tc = (lane & 3) * 2;
#pragma unroll
    for (int i = 0; i < 4; i++) {
#pragma unroll
        for (int nj = 0; nj < 4; nj++) {
            const int m0 = t0 + wm0 + i * 16 + tr;
            const int n  = o0 + wn0 + nj * 8 + tc;
            float2 v0 = make_float2(acc[i][nj][0], acc[i][nj][1]);
            float2 v1 = make_float2(acc[i][nj][2], acc[i][nj][3]);
            size_t base = ((size_t)(n >> 6) * T_DIM) * HD_DIM + (n & 63);
            if (z < 2) {
                float* C = z == 0 ? g_Q : g_K;
                *(float2*)&C[base + (size_t)m0 * HD_DIM]       = v0;
                *(float2*)&C[base + (size_t)(m0 + 8) * HD_DIM] = v1;
            } else {
                uint32_t h0 = pack_bf2(v0.x, v0.y);
                uint32_t h1 = pack_bf2(v1.x, v1.y);
                uint32_t l0 = pack_bf2(v0.x - bf_lo(h0), v0.y - bf_hi(h0));
                uint32_t l1 = pack_bf2(v1.x - bf_lo(h1), v1.y - bf_hi(h1));
                *(uint32_t*)&g_Vh[base + (size_t)m0 * HD_DIM]       = h0;
                *(uint32_t*)&g_Vh[base + (size_t)(m0 + 8) * HD_DIM] = h1;
                *(uint32_t*)&g_Vl[base + (size_t)m0 * HD_DIM]       = l0;
                *(uint32_t*)&g_Vl[base + (size_t)(m0 + 8) * HD_DIM] = l1;
            }
        }
    }
}

// Output projection: out = O * Wo^T (both tf32-rounded fp32)
__global__ __launch_bounds__(256, 2) void gemm_out_kernel(float* __restrict__ C)
{
    extern __shared__ char smem[];
    const uint32_t sb = s2u(smem);
    const int tid = threadIdx.x;
    const int t0 = blockIdx.x * 128;
    const int o0 = blockIdx.y * 128;

    float acc[4][4][4];
    gemm_mainloop32(sb, g_O32, g_wo32, t0, o0, tid, acc);

    const int lane = tid & 31;
    const int w = tid >> 5;
    const int wm0 = (w >> 2) * 64, wn0 = (w & 3) * 32;
    const int tr = lane >> 2, tc = (lane & 3) * 2;
#pragma unroll
    for (int i = 0; i < 4; i++) {
#pragma unroll
        for (int nj = 0; nj < 4; nj++) {
            const int m0 = t0 + wm0 + i * 16 + tr;
            const int n  = o0 + wn0 + nj * 8 + tc;
            *(float2*)&C[(size_t)m0 * D_DIM + n] =
                make_float2(acc[i][nj][0], acc[i][nj][1]);
            *(float2*)&C[(size_t)(m0 + 8) * D_DIM + n] =
                make_float2(acc[i][nj][2], acc[i][nj][3]);
        }
    }
}

// ---------------------------------------------------------------------------
// Tensor-core flash attention, bf16 hi/lo.  64-row K/V stages, 2 CTAs/SM,
// single barrier per block (wait0 -> barrier -> issue(kb+1) -> compute),
// bias rows prefetched into registers before the S-matmul.
// ---------------------------------------------------------------------------
#define AROWB   144
#define ATILE_Q (128 * AROWB)
#define KTILE   (64 * AROWB)
#define ASTG    (4 * KTILE)
#define ATT_SMEM (2 * ATILE_Q + 2 * ASTG)   // 110592 B
#define LOG2E 1.4426950408889634f

__device__ __forceinline__ void a_load_stage64(
    uint32_t st, const __nv_bfloat16* __restrict__ Kh, const __nv_bfloat16* __restrict__ Kl,
    const __nv_bfloat16* __restrict__ Vh, const __nv_bfloat16* __restrict__ Vl,
    int k0, int tid)
{
#pragma unroll
    for (int i = 0; i < 2; i++) {
        int q = tid + i * 256;
        int row = q >> 3, cc = q & 7;
        uint32_t so = row * AROWB + cc * 16;
        size_t g = (size_t)(k0 + row) * HD_DIM + cc * 8;
        cp16(st + so,             Kh + g);
        cp16(st + KTILE + so,     Kl + g);
        cp16(st + 2 * KTILE + so, Vh + g);
        cp16(st + 3 * KTILE + so, Vl + g);
    }
}

__global__ __launch_bounds__(256, 2) void attn_tc_kernel(
    const float* __restrict__ modw, const float* __restrict__ temps)
{
    extern __shared__ char smem[];
    const uint32_t sb = s2u(smem);
    const uint32_t sQh = sb, sQl = sb + ATILE_Q;
    const uint32_t sStage = sb + 2 * ATILE_Q;

    const int tid  = threadIdx.x;
    const int w    = tid >> 5;
    const int lane = tid & 31;
    const int qb = gridDim.x - 1 - blockIdx.x;
    const int h  = blockIdx.y;
    const int q0 = qb * 128;

    const float wgt = modw[c_h2m[h]];
    const float A1  = 0.125f * temps[h] * wgt * LOG2E;
    const float B1  = wgt * LOG2E;

    const __nv_bfloat16* Qhg = g_Qh + ((size_t)h * T_DIM + q0) * HD_DIM;
    const __nv_bfloat16* Qlg = g_Ql + ((size_t)h * T_DIM + q0) * HD_DIM;
    const __nv_bfloat16* Khg = g_Kh + (size_t)h * T_DIM * HD_DIM;
    const __nv_bfloat16* Klg = g_Kl + (size_t)h * T_DIM * HD_DIM;
    const __nv_bfloat16* Vhg = g_Vh + (size_t)h * T_DIM * HD_DIM;
    const __nv_bfloat16* Vlg = g_Vl + (size_t)h * T_DIM * HD_DIM;

    // Prologue: Q + stage0, ONE commit group
#pragma unroll
    for (int i = 0; i < 4; i++) {
        int q = tid + i * 256;
        int row = q >> 3, cc = q & 7;
        uint32_t so = row * AROWB + cc * 16;
        size_t g = (size_t)row * HD_DIM + cc * 8;
        cp16(sQh + so, Qhg + g);
        cp16(sQl + so, Qlg + g);
    }
    a_load_stage64(sStage, Khg, Klg, Vhg, Vlg, 0, tid);
    cp_commit();

    const int wq  = w * 16;
    const int lm  = lane & 15;
    const uint32_t kboff = (uint32_t)(lane >> 4) * 16;
    const int r   = lane >> 2;
    const int c2  = (lane & 3) * 2;
    const int qr0 = q0 + wq + r;
    const int qr1 = qr0 + 8;

    float m0 = -1e30f, m1 = -1e30f, l0 = 0.f, l1 = 0.f;
    float o[8][4];
#pragma unroll
    for (int j = 0; j < 8; j++)
#pragma unroll
        for (int q = 0; q < 4; q++) o[j][q] = 0.f;

    const uint32_t aQh = sQh + (uint32_t)(wq + lm) * AROWB + kboff;
    const uint32_t aQl = sQl + (uint32_t)(wq + lm) * AROWB + kboff;

    const int nkb = 2 * qb + 2;

    for (int kb = 0; kb < nkb; kb++) {
        cp_wait0();                      // my stage-kb copies done
        __syncthreads();                 // all copies visible; compute(kb-1) done
        if (kb + 1 < nkb) {
            a_load_stage64(sStage + (uint32_t)((kb + 1) & 1) * ASTG,
                           Khg, Klg, Vhg, Vlg, (kb + 1) * 64, tid);
            cp_commit();
        }
        const uint32_t st = sStage + (uint32_t)(kb & 1) * ASTG;
        const bool diag = (kb >= nkb - 2);
        const int k0 = kb * 64;

        // Bias prefetch: 16 bf16x2 loads issued before the S-matmul
        const __nv_bfloat16* br0 = g_cb + (size_t)qr0 * T_DIM + k0;
        const __nv_bfloat16* br1 = g_cb + (size_t)qr1 * T_DIM + k0;
        uint32_t bb0[8], bb1[8];
#pragma unroll
        for (int j = 0; j < 8; j++) {
            bb0[j] = *(const uint32_t*)(br0 + j * 8 + c2);
            bb1[j] = *(const uint32_t*)(br1 + j * 8 + c2);
        }

        float s[8][4];
#pragma unroll
        for (int j = 0; j < 8; j++)
#pragma unroll
            for (int q = 0; q < 4; q++) s[j][q] = 0.f;

#pragma unroll
        for (int ks = 0; ks < 4; ks++) {
            const uint32_t ko = (uint32_t)ks * 32;
            uint32_t ah[4], al[4];
            ldm_x4(ah, aQh + ko);
            ldm_x4(al, aQl + ko);
#pragma unroll
            for (int ng = 0; ng < 4; ng++) {
                uint32_t bh[4], bl[4];
                const uint32_t aK = st + (uint32_t)(ng * 16 + lm) * AROWB + kboff + ko;
                ldm_x4(bh, aK);
                ldm_x4(bl, aK + KTILE);
                mma16816(s[2 * ng],     ah, bh[0], bh[2]);
                mma16816(s[2 * ng + 1], ah, bh[1], bh[3]);
                mma16816(s[2 * ng],     ah, bl[0], bl[2]);
                mma16816(s[2 * ng + 1], ah, bl[1], bl[3]);
                mma16816(s[2 * ng],     al, bh[0], bh[2]);
                mma16816(s[2 * ng + 1], al, bh[1], bh[3]);
            }
        }

        float vmax0 = -1e30f, vmax1 = -1e30f;
#pragma unroll
        for (int j = 0; j < 8; j++) {
            const int kc = j * 8 + c2;
            float2 b0 = __bfloat1622float2(*(const __nv_bfloat162*)&bb0[j]);
            float2 b1 = __bfloat1622float2(*(const __nv_bfloat162*)&bb1[j]);
            s[j][0] = s[j][0] * A1 + b0.x * B1;
            s[j][1] = s[j][1] * A1 + b0.y * B1;
            s[j][2] = s[j][2] * A1 + b1.x * B1;
            s[j][3] = s[j][3] * A1 + b1.y * B1;
            if (diag) {
                const int ka = k0 + kc;
                if (ka > qr0)     s[j][0] = -1e30f;
                if (ka + 1 > qr0) s[j][1] = -1e30f;
                if (ka > qr1)     s[j][2] = -1e30f;
                if (ka + 1 > qr1) s[j][3] = -1e30f;
            }
            vmax0 = fmaxf(vmax0, fmaxf(s[j][0], s[j][1]));
            vmax1 = fmaxf(vmax1, fmaxf(s[j][2], s[j][3]));
        }
        vmax0 = fmaxf(vmax0, __shfl_xor_sync(0xffffffffu, vmax0, 1));
        vmax0 = fmaxf(vmax0, __shfl_xor_sync(0xffffffffu, vmax0, 2));
        vmax1 = fmaxf(vmax1, __shfl_xor_sync(0xffffffffu, vmax1, 1));
        vmax1 = fmaxf(vmax1, __shfl_xor_sync(0xffffffffu, vmax1, 2));

        const float mn0 = fmaxf(m0, vmax0);
        const float mn1 = fmaxf(m1, vmax1);
        const float al0 = ex2(m0 - mn0);
        const float al1 = ex2(m1 - mn1);
        m0 = mn0; m1 = mn1;

        float rs0 = 0.f, rs1 = 0.f;
#pragma unroll
        for (int j = 0; j < 8; j++) {
            s[j][0] = ex2(s[j][0] - mn0);
            s[j][1] = ex2(s[j][1] - mn0);
            s[j][2] = ex2(s[j][2] - mn1);
            s[j][3] = ex2(s[j][3] - mn1);
            rs0 += s[j][0] + s[j][1];
            rs1 += s[j][2] + s[j][3];
        }
        rs0 += __shfl_xor_sync(0xffffffffu, rs0, 1);
        rs0 += __shfl_xor_sync(0xffffffffu, rs0, 2);
        rs1 += __shfl_xor_sync(0xffffffffu, rs1, 1);
        rs1 += __shfl_xor_sync(0xffffffffu, rs1, 2);
        l0 = l0 * al0 + rs0;
        l1 = l1 * al1 + rs1;

#pragma unroll
        for (int j = 0; j < 8; j++) {
            o[j][0] *= al0; o[j][1] *= al0;
            o[j][2] *= al1; o[j][3] *= al1;
        }

#pragma unroll
        for (int ks = 0; ks < 4; ks++) {
            uint32_t ph[4], pl[4];
#pragma unroll
            for (int u = 0; u < 2; u++) {
                const int j = 2 * ks + u;
                uint32_t d0 = pack_bf2(s[j][0], s[j][1]);
                uint32_t d1 = pack_bf2(s[j][2], s[j][3]);
                ph[u]     = d0;  ph[2 + u] = d1;
                pl[u]     = pack_bf2(s[j][0] - bf_lo(d0), s[j][1] - bf_hi(d0));
                pl[2 + u] = pack_bf2(s[j][2] - bf_lo(d1), s[j][3] - bf_hi(d1));
            }
            uint32_t pa_h[4] = { ph[0], ph[2], ph[1], ph[3] };
            uint32_t pa_l[4] = { pl[0], pl[2], pl[1], pl[3] };
#pragma unroll
            for (int nv = 0; nv < 2; nv++) {
#pragma unroll
                for (int half = 0; half < 2; half++) {
                    const int n0 = nv * 32 + half * 16;
                    const uint32_t aV = st + 2 * KTILE
                        + (uint32_t)(ks * 16 + lm) * AROWB
                        + (uint32_t)(n0 + ((lane >> 4) * 8)) * 2;
                    uint32_t vh[4], vl[4];
                    ldm_x4_t(vh, aV);
                    ldm_x4_t(vl, aV + KTILE);
                    const int jt = nv * 4 + half * 2;
                    mma16816(o[jt],     pa_h, vh[0], vh[1]);
                    mma16816(o[jt + 1], pa_h, vh[2], vh[3]);
                    mma16816(o[jt],     pa_h, vl[0], vl[1]);
                    mma16816(o[jt + 1], pa_h, vl[2], vl[3]);
                    mma16816(o[jt],     pa_l, vh[0], vh[1]);
                    mma16816(o[jt + 1], pa_l, vh[2], vh[3]);
                }
            }
        }
    }

    // epilogue: normalize, RNA-round to tf32, write fp32 [T][D]
    const float inv0 = 1.f / l0, inv1 = 1.f / l1;
#pragma unroll
    for (int j = 0; j < 8; j++) {
        const int d = j * 8 + c2;
        size_t i0 = (size_t)qr0 * D_DIM + h * HD_DIM + d;
        size_t i1 = (size_t)qr1 * D_DIM + h * HD_DIM + d;
        *(float2*)&g_O32[i0] = make_float2(
            __uint_as_float(f2tf(o[j][0] * inv0)),
            __uint_as_float(f2tf(o[j][1] * inv0)));
        *(float2*)&g_O32[i1] = make_float2(
            __uint_as_float(f2tf(o[j][2] * inv1)),
            __uint_as_float(f2tf(o[j][3] * inv1)));
    }
}

// ---------------------------------------------------------------------------
extern "C" void kernel_launch(void* const* d_in, const int* in_sizes, int n_in,
                              void* d_out, int out_size)
{
    const float* x  = (const float*)d_in[0];
    const float* cb = (const float*)d_in[2];
    const float* mw = (const float*)d_in[3];
    const float* Wq = (const float*)d_in[4];
    const float* Wk = (const float*)d_in[5];
    const float* Wv = (const float*)d_in[6];
    const float* Wo = (const float*)d_in[7];
    const float* ts = (const float*)d_in[8];
    float* out = (float*)d_out;

    cudaFuncSetAttribute(gemm_qkv_kernel,
                         cudaFuncAttributeMaxDynamicSharedMemorySize, GEMM_SMEM);
    cudaFuncSetAttribute(gemm_out_kernel,
                         cudaFuncAttributeMaxDynamicSharedMemorySize, GEMM_SMEM);
    cudaFuncSetAttribute(attn_tc_kernel,
                         cudaFuncAttributeMaxDynamicSharedMemorySize, ATT_SMEM);

    roundA_kernel<<<dim3(4096, 3), 256>>>((const float4*)x, (const float4*)Wq,
                                          (const float4*)Wk);
    roundB_kernel<<<dim3(4096, 2), 256>>>((const float4*)Wv, (const float4*)Wo);
    bias_bf16_kernel<<<8192, 256>>>((const float2*)cb);

    gemm_qkv_kernel<<<dim3(16, 16, 3), 256, GEMM_SMEM>>>();

    rope_split_kernel<<<(H_NUM * T_DIM * 32) / 256, 256>>>();

    attn_tc_kernel<<<dim3(T_DIM / 128, H_NUM), 256, ATT_SMEM>>>(mw, ts);

    gemm_out_kernel<<<dim3(16, 16), 256, GEMM_SMEM>>>(out);
}